// round 10
// baseline (speedup 1.0000x reference)
#include <cuda_runtime.h>
#include <cuda_bf16.h>
#include <math.h>
#include <stdint.h>

// ---------------- problem constants ----------------
#define B_  2
#define S_  4096
#define H_  2048
#define R_  2048
#define NB_ 16
#define BW_ 128
#define CW_ 4
#define M_  (B_*S_)        // 8192
#define NCHUNK 16
#define CHL (S_/NCHUNK)    // 256
#define NCH (B_*R_)        // 4096
#define KDIM 2048
#define KC  64             // K elements per SMEM chunk
#define NKC (KDIM/KC)      // 32 chunks

// ---------------- scratch (device globals; no allocations allowed) ----------
__device__ float g_xr[(size_t)M_*R_];
__device__ float g_gy[(size_t)M_*R_];
__device__ float g_xc[(size_t)M_*R_];
__device__ float g_av[(size_t)M_*R_];
__device__ float g_nx[(size_t)M_*R_];
__device__ float g_Asum[NCH*NCHUNK];
__device__ float g_Bsum[NCH*NCHUNK];
__device__ float g_carry[NCH*NCHUNK];

__device__ __nv_bfloat16 g_xh [(size_t)M_*H_];
__device__ __nv_bfloat16 g_xl [(size_t)M_*H_];
__device__ __nv_bfloat16 g_wxyh[(size_t)2*R_*H_];
__device__ __nv_bfloat16 g_wxyl[(size_t)2*R_*H_];
__device__ __nv_bfloat16 g_wrh[(size_t)H_*R_];
__device__ __nv_bfloat16 g_wrl[(size_t)H_*R_];
__device__ __nv_bfloat16 g_hgh[(size_t)M_*R_];
__device__ __nv_bfloat16 g_hgl[(size_t)M_*R_];

// ---------------- helpers ----------------------------------------------------
__device__ __forceinline__ uint32_t smem_to_u32(const void* p) {
    uint32_t a;
    asm("{ .reg .u64 t; cvta.to.shared.u64 t, %1; cvt.u32.u64 %0, t; }"
        : "=r"(a) : "l"(p));
    return a;
}

__device__ __forceinline__ void ldsm4(uint32_t addr,
    uint32_t& r0, uint32_t& r1, uint32_t& r2, uint32_t& r3)
{
    asm volatile("ldmatrix.sync.aligned.m8n8.x4.shared.b16 {%0,%1,%2,%3}, [%4];"
        : "=r"(r0), "=r"(r1), "=r"(r2), "=r"(r3) : "r"(addr));
}

__device__ __forceinline__ void mma16816(float* c,
    const uint32_t* a, uint32_t b0, uint32_t b1)
{
    asm volatile(
        "mma.sync.aligned.m16n8k16.row.col.f32.bf16.bf16.f32 "
        "{%0,%1,%2,%3}, {%4,%5,%6,%7}, {%8,%9}, {%0,%1,%2,%3};"
        : "+f"(c[0]), "+f"(c[1]), "+f"(c[2]), "+f"(c[3])
        : "r"(a[0]), "r"(a[1]), "r"(a[2]), "r"(a[3]), "r"(b0), "r"(b1));
}

__device__ __forceinline__ void split1(float v, __nv_bfloat16& h, __nv_bfloat16& l)
{
    h = __float2bfloat16(v);
    l = __float2bfloat16(v - __bfloat162float(h));
}

// ---------------- fp32 -> (bf16 hi, bf16 lo) split --------------------------
template <int DST>
__global__ void split_kernel(const float4* __restrict__ src)
{
    int i = blockIdx.x * 256 + threadIdx.x;
    float4 v = src[i];
    __nv_bfloat16 h0, h1, h2, h3, l0, l1, l2, l3;
    split1(v.x, h0, l0); split1(v.y, h1, l1);
    split1(v.z, h2, l2); split1(v.w, h3, l3);
    uint2 hv, lv;
    hv.x = (uint32_t)__bfloat16_as_ushort(h0) | ((uint32_t)__bfloat16_as_ushort(h1) << 16);
    hv.y = (uint32_t)__bfloat16_as_ushort(h2) | ((uint32_t)__bfloat16_as_ushort(h3) << 16);
    lv.x = (uint32_t)__bfloat16_as_ushort(l0) | ((uint32_t)__bfloat16_as_ushort(l1) << 16);
    lv.y = (uint32_t)__bfloat16_as_ushort(l2) | ((uint32_t)__bfloat16_as_ushort(l3) << 16);
    __nv_bfloat16 *hp, *lp;
    if (DST == 0)      { hp = g_xh;   lp = g_xl;   }
    else if (DST == 1) { hp = g_wxyh; lp = g_wxyl; }
    else               { hp = g_wrh;  lp = g_wrl;  }
    *(uint2*)(hp + 4ull * i) = hv;
    *(uint2*)(lp + 4ull * i) = lv;
}

// ---------------- HMMA split-bf16 GEMM (TN) ----------------------------------
// C[m,n] = sum_k A[m,k]*B[n,k]; A:[M,2048], B:[N,2048] row-major.
// Tile 128x128, 8 warps (4 x 2), warp tile 32x64. BK=64 double-buffered via
// cp.async. 3-product split: Ah*Bh + Ah*Bl + Al*Bh, fp32 accumulate.
// SMEM stage: Ah | Al | Bh | Bl, each 128 rows x 128 bytes, xor-swizzled.
#define TILEB   16384
#define STAGEB  (4*TILEB)
#define GEMM_SMEM (2*STAGEB)   // 131072

__device__ __forceinline__ void load_tile_async(
    const __nv_bfloat16* __restrict__ g, int row0, int kc,
    uint32_t sdst, int tid)
{
#pragma unroll
    for (int i = 0; i < 4; i++) {
        int u = i * 256 + tid;          // 0..1023 16B units
        int row = u >> 3;               // 0..127
        int un  = u & 7;                // unit within 128B row
        const __nv_bfloat16* src = g + (size_t)(row0 + row) * KDIM + kc * KC + un * 8;
        uint32_t dst = sdst + row * 128 + ((un ^ (row & 7)) * 16);
        asm volatile("cp.async.cg.shared.global [%0], [%1], 16;"
            :: "r"(dst), "l"(src) : "memory");
    }
}

// EPI 1: GEMM1 (A=x, B=W_xy): n<R_ -> g_xr ; n>=R_ -> gelu -> g_gy
// EPI 2: GEMM2 (A=hg, B=W_resid): -> Cout (ldc=H_)
template <int EPI>
__global__ __launch_bounds__(256) void gemm_tc(float* __restrict__ Cout)
{
    extern __shared__ char smem[];
    const uint32_t smem_u = smem_to_u32(smem);
    const int tid  = threadIdx.x;
    const int lane = tid & 31;
    const int wm   = (tid >> 5) & 3;    // warp row 0..3  (32 rows each)
    const int wn   = tid >> 7;          // warp col 0..1  (64 cols each)
    const int bm = blockIdx.y * 128;
    const int bn = blockIdx.x * 128;

    const __nv_bfloat16 *Ah, *Al, *Bh, *Bl;
    if (EPI == 1) { Ah = g_xh;  Al = g_xl;  Bh = g_wxyh; Bl = g_wxyl; }
    else          { Ah = g_hgh; Al = g_hgl; Bh = g_wrh;  Bl = g_wrl;  }

    float acc[2][8][4];
#pragma unroll
    for (int mb = 0; mb < 2; mb++)
#pragma unroll
        for (int n8 = 0; n8 < 8; n8++)
#pragma unroll
            for (int q = 0; q < 4; q++) acc[mb][n8][q] = 0.f;

    // prologue: chunk 0 -> stage 0
    {
        uint32_t sb = smem_u;
        load_tile_async(Ah, bm, 0, sb,             tid);
        load_tile_async(Al, bm, 0, sb + TILEB,     tid);
        load_tile_async(Bh, bn, 0, sb + 2*TILEB,   tid);
        load_tile_async(Bl, bn, 0, sb + 3*TILEB,   tid);
        asm volatile("cp.async.commit_group;" ::: "memory");
    }

    // precomputed lane addressing pieces
    const int a_row = wm * 32 + (lane & 15);          // + mb*16
    const int a_hf  = lane >> 4;                      // k half unit
    const int b_row = wn * 64 + (lane & 7) + ((lane >> 4) << 3);  // + np*16
    const int b_hf  = (lane >> 3) & 1;

    for (int c = 0; c < NKC; c++) {
        if (c + 1 < NKC) {
            uint32_t sb = smem_u + ((c + 1) & 1) * STAGEB;
            load_tile_async(Ah, bm, c + 1, sb,             tid);
            load_tile_async(Al, bm, c + 1, sb + TILEB,     tid);
            load_tile_async(Bh, bn, c + 1, sb + 2*TILEB,   tid);
            load_tile_async(Bl, bn, c + 1, sb + 3*TILEB,   tid);
            asm volatile("cp.async.commit_group;" ::: "memory");
            asm volatile("cp.async.wait_group 1;" ::: "memory");
        } else {
            asm volatile("cp.async.wait_group 0;" ::: "memory");
        }
        __syncthreads();

        const uint32_t sA = smem_u + (c & 1) * STAGEB;
        const uint32_t sB = sA + 2*TILEB;

#pragma unroll
        for (int ks = 0; ks < 4; ks++) {
            uint32_t ah[2][4], al[2][4];
#pragma unroll
            for (int mb = 0; mb < 2; mb++) {
                int row = a_row + mb * 16;
                int un  = ks * 2 + a_hf;
                uint32_t off = row * 128 + ((un ^ (row & 7)) * 16);
                ldsm4(sA + off,         ah[mb][0], ah[mb][1], ah[mb][2], ah[mb][3]);
                ldsm4(sA + TILEB + off, al[mb][0], al[mb][1], al[mb][2], al[mb][3]);
            }
#pragma unroll
            for (int np = 0; np < 4; np++) {
                int row = b_row + np * 16;
                int un  = ks * 2 + b_hf;
                uint32_t off = row * 128 + ((un ^ (row & 7)) * 16);
                uint32_t bh0, bh1, bh2, bh3, bl0, bl1, bl2, bl3;
                ldsm4(sB + off,         bh0, bh1, bh2, bh3);
                ldsm4(sB + TILEB + off, bl0, bl1, bl2, bl3);
#pragma unroll
                for (int mb = 0; mb < 2; mb++) {
                    mma16816(acc[mb][np*2+0], ah[mb], bh0, bh1);
                    mma16816(acc[mb][np*2+1], ah[mb], bh2, bh3);
                    mma16816(acc[mb][np*2+0], ah[mb], bl0, bl1);
                    mma16816(acc[mb][np*2+1], ah[mb], bl2, bl3);
                    mma16816(acc[mb][np*2+0], al[mb], bh0, bh1);
                    mma16816(acc[mb][np*2+1], al[mb], bh2, bh3);
                }
            }
        }
        __syncthreads();
    }

    // ---------------- epilogue ----------------
    const int mrow0 = bm + wm * 32 + (lane >> 2);
    const int ncol0 = bn + wn * 64 + (lane & 3) * 2;
#pragma unroll
    for (int mb = 0; mb < 2; mb++) {
#pragma unroll
        for (int n8 = 0; n8 < 8; n8++) {
            int n = ncol0 + n8 * 8;
            int m0 = mrow0 + mb * 16;
            float2 v0 = make_float2(acc[mb][n8][0], acc[mb][n8][1]);
            float2 v1 = make_float2(acc[mb][n8][2], acc[mb][n8][3]);
            if (EPI == 2) {
                *(float2*)(Cout + (size_t)m0 * H_ + n)       = v0;
                *(float2*)(Cout + (size_t)(m0 + 8) * H_ + n) = v1;
            } else if (bn < R_) {
                *(float2*)(g_xr + (size_t)m0 * R_ + n)       = v0;
                *(float2*)(g_xr + (size_t)(m0 + 8) * R_ + n) = v1;
            } else {
                v0.x = 0.5f * v0.x * (1.0f + erff(v0.x * 0.7071067811865476f));
                v0.y = 0.5f * v0.y * (1.0f + erff(v0.y * 0.7071067811865476f));
                v1.x = 0.5f * v1.x * (1.0f + erff(v1.x * 0.7071067811865476f));
                v1.y = 0.5f * v1.y * (1.0f + erff(v1.y * 0.7071067811865476f));
                *(float2*)(g_gy + (size_t)m0 * R_ + (n - R_))       = v0;
                *(float2*)(g_gy + (size_t)(m0 + 8) * R_ + (n - R_)) = v1;
            }
        }
    }
}

// ---------------- causal depthwise conv (CW=4) ------------------------------
__global__ void conv_kernel(const float* __restrict__ conv_w,
                            const float* __restrict__ conv_b)
{
    size_t idx = (size_t)blockIdx.x * blockDim.x + threadIdx.x;
    int r = (int)(idx & (R_ - 1));
    size_t row = idx >> 11;
    int t = (int)(row & (S_ - 1));
    int b = (int)(row >> 12);
    float acc = conv_b[r];
#pragma unroll
    for (int i = 0; i < CW_; i++) {
        int tt = t - (CW_ - 1) + i;
        if (tt >= 0)
            acc += conv_w[i * R_ + r] * g_xr[((size_t)(b * S_ + tt)) * R_ + r];
    }
    g_xc[idx] = acc;
}

// ---------------- block-diag gate GEMMs + RG-LRU elementwise ----------------
__global__ __launch_bounds__(256) void blockdiag_gates(
    const float* __restrict__ igw, const float* __restrict__ igb,
    const float* __restrict__ agw, const float* __restrict__ agb,
    const float* __restrict__ a_param)
{
    __shared__ __align__(16) float Xs[16][128];
    __shared__ __align__(16) float Wi[16][128];
    __shared__ __align__(16) float Wa[16][128];

    const int nb = blockIdx.x;
    const int bm = blockIdx.y * 128;
    const int tid = threadIdx.x;
    const int tx = tid & 15, ty = tid >> 4;
    const int lr = tid >> 2, lc = (tid & 3) << 2;
    const int wr = tid >> 5, wc = (tid & 31) << 2;

    const float* wip = igw + (size_t)nb * BW_ * BW_;
    const float* wap = agw + (size_t)nb * BW_ * BW_;

    float accI[8][8], accA[8][8];
#pragma unroll
    for (int i = 0; i < 8; i++)
#pragma unroll
        for (int j = 0; j < 8; j++) { accI[i][j] = 0.f; accA[i][j] = 0.f; }

    for (int k0 = 0; k0 < BW_; k0 += 16) {
        float4 x0 = *(const float4*)(g_xc + (size_t)(bm + lr)      * R_ + nb*BW_ + k0 + lc);
        float4 x1 = *(const float4*)(g_xc + (size_t)(bm + lr + 64) * R_ + nb*BW_ + k0 + lc);
        float4 wi0 = *(const float4*)(wip + (size_t)(k0 + wr)     * BW_ + wc);
        float4 wi1 = *(const float4*)(wip + (size_t)(k0 + wr + 8) * BW_ + wc);
        float4 wa0 = *(const float4*)(wap + (size_t)(k0 + wr)     * BW_ + wc);
        float4 wa1 = *(const float4*)(wap + (size_t)(k0 + wr + 8) * BW_ + wc);
        __syncthreads();
        Xs[lc+0][lr] = x0.x; Xs[lc+1][lr] = x0.y; Xs[lc+2][lr] = x0.z; Xs[lc+3][lr] = x0.w;
        Xs[lc+0][lr+64] = x1.x; Xs[lc+1][lr+64] = x1.y; Xs[lc+2][lr+64] = x1.z; Xs[lc+3][lr+64] = x1.w;
        *(float4*)(&Wi[wr][wc])     = wi0;
        *(float4*)(&Wi[wr + 8][wc]) = wi1;
        *(float4*)(&Wa[wr][wc])     = wa0;
        *(float4*)(&Wa[wr + 8][wc]) = wa1;
        __syncthreads();

#pragma unroll
        for (int kk = 0; kk < 16; kk++) {
            float ra[8], ri[8], rc[8];
            *(float4*)(&ra[0]) = *(const float4*)(&Xs[kk][ty*4]);
            *(float4*)(&ra[4]) = *(const float4*)(&Xs[kk][64 + ty*4]);
            *(float4*)(&ri[0]) = *(const float4*)(&Wi[kk][tx*4]);
            *(float4*)(&ri[4]) = *(const float4*)(&Wi[kk][64 + tx*4]);
            *(float4*)(&rc[0]) = *(const float4*)(&Wa[kk][tx*4]);
            *(float4*)(&rc[4]) = *(const float4*)(&Wa[kk][64 + tx*4]);
#pragma unroll
            for (int i = 0; i < 8; i++)
#pragma unroll
                for (int j = 0; j < 8; j++) {
                    accI[i][j] += ra[i] * ri[j];
                    accA[i][j] += ra[i] * rc[j];
                }
        }
    }

#pragma unroll
    for (int i = 0; i < 8; i++) {
        int m = bm + ((i < 4) ? (ty*4 + i) : (64 + ty*4 + i - 4));
#pragma unroll
        for (int j = 0; j < 8; j++) {
            int col = (j < 4) ? (tx*4 + j) : (64 + tx*4 + j - 4);
            int r = nb * BW_ + col;
            float xg = accI[i][j] + igb[nb * BW_ + col];
            float ag = accA[i][j] + agb[nb * BW_ + col];
            float ap = a_param[r];
            float sp = (ap > 20.f) ? ap : log1pf(expf(ap));
            float ga = 1.f / (1.f + expf(-ag));
            float la = -8.f * ga * sp;
            float a  = expf(la);
            float mult = sqrtf(-expm1f(2.f * la));
            float gx = 1.f / (1.f + expf(-xg));
            float xv = g_xc[(size_t)m * R_ + r];
            g_av[(size_t)m * R_ + r] = a;
            g_nx[(size_t)m * R_ + r] = xv * gx * mult;
        }
    }
}

// ---------------- chunked linear-recurrence scan ----------------------------
__global__ void scanA()
{
    int r = blockIdx.x * 256 + threadIdx.x;
    int chunk = blockIdx.y;
    int b = blockIdx.z;
    size_t base = ((size_t)(b * S_ + chunk * CHL)) * R_ + r;
    const float* __restrict__ pa = g_av + base;
    const float* __restrict__ px = g_nx + base;
    float A = 1.f, Bv = 0.f;
#pragma unroll 4
    for (int t = 0; t < CHL; t++) {
        float av = pa[(size_t)t * R_];
        float xv = px[(size_t)t * R_];
        Bv = av * Bv + xv;
        A *= av;
    }
    int ch = b * R_ + r;
    g_Asum[ch * NCHUNK + chunk] = A;
    g_Bsum[ch * NCHUNK + chunk] = Bv;
}

__global__ void scanB()
{
    int ch = blockIdx.x * 256 + threadIdx.x;
    float h = 0.f;
#pragma unroll
    for (int c = 0; c < NCHUNK; c++) {
        g_carry[ch * NCHUNK + c] = h;
        h = g_Asum[ch * NCHUNK + c] * h + g_Bsum[ch * NCHUNK + c];
    }
}

__global__ void scanC()
{
    int r = blockIdx.x * 256 + threadIdx.x;
    int chunk = blockIdx.y;
    int b = blockIdx.z;
    size_t base = ((size_t)(b * S_ + chunk * CHL)) * R_ + r;
    const float* __restrict__ pa = g_av + base;
    const float* __restrict__ px = g_nx + base;
    const float* __restrict__ pg = g_gy + base;
    __nv_bfloat16* __restrict__ ph = g_hgh + base;
    __nv_bfloat16* __restrict__ pl = g_hgl + base;
    int ch = b * R_ + r;
    float h = g_carry[ch * NCHUNK + chunk];
#pragma unroll 4
    for (int t = 0; t < CHL; t++) {
        float av = pa[(size_t)t * R_];
        float xv = px[(size_t)t * R_];
        h = av * h + xv;
        float hg = h * pg[(size_t)t * R_];
        __nv_bfloat16 hh, hl;
        split1(hg, hh, hl);
        ph[(size_t)t * R_] = hh;
        pl[(size_t)t * R_] = hl;
    }
}

// ---------------- host launcher ---------------------------------------------
extern "C" void kernel_launch(void* const* d_in, const int* in_sizes, int n_in,
                              void* d_out, int out_size)
{
    const float* x       = (const float*)d_in[0];
    const float* W_xy    = (const float*)d_in[1];
    const float* ig_w    = (const float*)d_in[2];
    const float* ig_b    = (const float*)d_in[3];
    const float* ag_w    = (const float*)d_in[4];
    const float* ag_b    = (const float*)d_in[5];
    const float* a_param = (const float*)d_in[6];
    const float* conv_w  = (const float*)d_in[7];
    const float* conv_b  = (const float*)d_in[8];
    const float* W_resid = (const float*)d_in[9];
    float* out = (float*)d_out;

    cudaFuncSetAttribute(gemm_tc<1>, cudaFuncAttributeMaxDynamicSharedMemorySize, GEMM_SMEM);
    cudaFuncSetAttribute(gemm_tc<2>, cudaFuncAttributeMaxDynamicSharedMemorySize, GEMM_SMEM);

    // 0) split operands to bf16 hi/lo
    split_kernel<0><<<(M_ * H_ / 4) / 256, 256>>>((const float4*)x);
    split_kernel<1><<<(2 * R_ * H_ / 4) / 256, 256>>>((const float4*)W_xy);
    split_kernel<2><<<(H_ * R_ / 4) / 256, 256>>>((const float4*)W_resid);

    // 1) xy = x @ W_xy^T  (HMMA split-bf16; epilogue -> g_xr, gelu -> g_gy)
    {
        dim3 grid(2 * R_ / 128, M_ / 128);   // (32, 64)
        gemm_tc<1><<<grid, 256, GEMM_SMEM>>>(nullptr);
    }
    // 2) causal depthwise conv
    conv_kernel<<<(unsigned)((size_t)M_ * R_ / 256), 256>>>(conv_w, conv_b);
    // 3) block-diag gates + RG-LRU elementwise
    {
        dim3 grid(NB_, M_ / 128);
        blockdiag_gates<<<grid, 256>>>(ig_w, ig_b, ag_w, ag_b, a_param);
    }
    // 4) chunked scan, fused * gelu(y), bf16-split output
    {
        dim3 gA(R_ / 256, NCHUNK, B_);
        scanA<<<gA, 256>>>();
        scanB<<<NCH / 256, 256>>>();
        scanC<<<gA, 256>>>();
    }
    // 5) out = hg @ W_resid^T  (HMMA split-bf16)
    {
        dim3 grid(H_ / 128, M_ / 128);       // (16, 64)
        gemm_tc<2><<<grid, 256, GEMM_SMEM>>>(out);
    }
}

// round 11
// speedup vs baseline: 1.0013x; 1.0013x over previous
#include <cuda_runtime.h>
#include <cuda_bf16.h>
#include <math.h>
#include <stdint.h>

// ---------------- problem constants ----------------
#define B_  2
#define S_  4096
#define H_  2048
#define R_  2048
#define NB_ 16
#define BW_ 128
#define CW_ 4
#define M_  (B_*S_)        // 8192
#define NCHUNK 16
#define CHL (S_/NCHUNK)    // 256
#define NCH (B_*R_)        // 4096
#define KDIM 2048
#define KC  64             // K elements per SMEM chunk
#define NKC (KDIM/KC)      // 32 chunks

// ---------------- scratch (device globals; no allocations allowed) ----------
__device__ float g_xr[(size_t)M_*R_];
__device__ float g_gy[(size_t)M_*R_];
__device__ float g_xc[(size_t)M_*R_];
__device__ float g_av[(size_t)M_*R_];
__device__ float g_nx[(size_t)M_*R_];
__device__ float g_Asum[NCH*NCHUNK];
__device__ float g_Bsum[NCH*NCHUNK];
__device__ float g_carry[NCH*NCHUNK];

__device__ __nv_bfloat16 g_xh [(size_t)M_*H_];
__device__ __nv_bfloat16 g_xl [(size_t)M_*H_];
__device__ __nv_bfloat16 g_wxyh[(size_t)2*R_*H_];
__device__ __nv_bfloat16 g_wxyl[(size_t)2*R_*H_];
__device__ __nv_bfloat16 g_wrh[(size_t)H_*R_];
__device__ __nv_bfloat16 g_wrl[(size_t)H_*R_];
__device__ __nv_bfloat16 g_hgh[(size_t)M_*R_];
__device__ __nv_bfloat16 g_hgl[(size_t)M_*R_];

// ---------------- helpers ----------------------------------------------------
__device__ __forceinline__ uint32_t smem_to_u32(const void* p) {
    uint32_t a;
    asm("{ .reg .u64 t; cvta.to.shared.u64 t, %1; cvt.u32.u64 %0, t; }"
        : "=r"(a) : "l"(p));
    return a;
}

__device__ __forceinline__ void ldsm4(uint32_t addr,
    uint32_t& r0, uint32_t& r1, uint32_t& r2, uint32_t& r3)
{
    asm volatile("ldmatrix.sync.aligned.m8n8.x4.shared.b16 {%0,%1,%2,%3}, [%4];"
        : "=r"(r0), "=r"(r1), "=r"(r2), "=r"(r3) : "r"(addr));
}

__device__ __forceinline__ void mma16816(float* c,
    const uint32_t* a, uint32_t b0, uint32_t b1)
{
    asm volatile(
        "mma.sync.aligned.m16n8k16.row.col.f32.bf16.bf16.f32 "
        "{%0,%1,%2,%3}, {%4,%5,%6,%7}, {%8,%9}, {%0,%1,%2,%3};"
        : "+f"(c[0]), "+f"(c[1]), "+f"(c[2]), "+f"(c[3])
        : "r"(a[0]), "r"(a[1]), "r"(a[2]), "r"(a[3]), "r"(b0), "r"(b1));
}

__device__ __forceinline__ void split1(float v, __nv_bfloat16& h, __nv_bfloat16& l)
{
    h = __float2bfloat16(v);
    l = __float2bfloat16(v - __bfloat162float(h));
}

// ---------------- fp32 -> (bf16 hi, bf16 lo) split --------------------------
template <int DST>
__global__ void split_kernel(const float4* __restrict__ src)
{
    int i = blockIdx.x * 256 + threadIdx.x;
    float4 v = src[i];
    __nv_bfloat16 h0, h1, h2, h3, l0, l1, l2, l3;
    split1(v.x, h0, l0); split1(v.y, h1, l1);
    split1(v.z, h2, l2); split1(v.w, h3, l3);
    uint2 hv, lv;
    hv.x = (uint32_t)__bfloat16_as_ushort(h0) | ((uint32_t)__bfloat16_as_ushort(h1) << 16);
    hv.y = (uint32_t)__bfloat16_as_ushort(h2) | ((uint32_t)__bfloat16_as_ushort(h3) << 16);
    lv.x = (uint32_t)__bfloat16_as_ushort(l0) | ((uint32_t)__bfloat16_as_ushort(l1) << 16);
    lv.y = (uint32_t)__bfloat16_as_ushort(l2) | ((uint32_t)__bfloat16_as_ushort(l3) << 16);
    __nv_bfloat16 *hp, *lp;
    if (DST == 0)      { hp = g_xh;   lp = g_xl;   }
    else if (DST == 1) { hp = g_wxyh; lp = g_wxyl; }
    else               { hp = g_wrh;  lp = g_wrl;  }
    *(uint2*)(hp + 4ull * i) = hv;
    *(uint2*)(lp + 4ull * i) = lv;
}

// ---------------- HMMA split-bf16 GEMM (TN) ----------------------------------
// C[m,n] = sum_k A[m,k]*B[n,k]; A:[M,2048], B:[N,2048] row-major.
// Tile 128x128, 8 warps (4 x 2), warp tile 32x64. BK=64 double-buffered via
// cp.async. 3-product split: Ah*Bh + Ah*Bl + Al*Bh, fp32 accumulate.
// SMEM stage: Ah | Al | Bh | Bl, each 128 rows x 128 bytes, xor-swizzled.
#define TILEB   16384
#define STAGEB  (4*TILEB)
#define GEMM_SMEM (2*STAGEB)   // 131072

__device__ __forceinline__ void load_tile_async(
    const __nv_bfloat16* __restrict__ g, int row0, int kc,
    uint32_t sdst, int tid)
{
#pragma unroll
    for (int i = 0; i < 4; i++) {
        int u = i * 256 + tid;          // 0..1023 16B units
        int row = u >> 3;               // 0..127
        int un  = u & 7;                // unit within 128B row
        const __nv_bfloat16* src = g + (size_t)(row0 + row) * KDIM + kc * KC + un * 8;
        uint32_t dst = sdst + row * 128 + ((un ^ (row & 7)) * 16);
        asm volatile("cp.async.cg.shared.global [%0], [%1], 16;"
            :: "r"(dst), "l"(src) : "memory");
    }
}

// EPI 1: GEMM1 (A=x, B=W_xy): n<R_ -> g_xr ; n>=R_ -> gelu -> g_gy
// EPI 2: GEMM2 (A=hg, B=W_resid): -> Cout (ldc=H_)
template <int EPI>
__global__ __launch_bounds__(256) void gemm_tc(float* __restrict__ Cout)
{
    extern __shared__ char smem[];
    const uint32_t smem_u = smem_to_u32(smem);
    const int tid  = threadIdx.x;
    const int lane = tid & 31;
    const int wm   = (tid >> 5) & 3;    // warp row 0..3  (32 rows each)
    const int wn   = tid >> 7;          // warp col 0..1  (64 cols each)
    const int bm = blockIdx.y * 128;
    const int bn = blockIdx.x * 128;

    const __nv_bfloat16 *Ah, *Al, *Bh, *Bl;
    if (EPI == 1) { Ah = g_xh;  Al = g_xl;  Bh = g_wxyh; Bl = g_wxyl; }
    else          { Ah = g_hgh; Al = g_hgl; Bh = g_wrh;  Bl = g_wrl;  }

    float acc[2][8][4];
#pragma unroll
    for (int mb = 0; mb < 2; mb++)
#pragma unroll
        for (int n8 = 0; n8 < 8; n8++)
#pragma unroll
            for (int q = 0; q < 4; q++) acc[mb][n8][q] = 0.f;

    // prologue: chunk 0 -> stage 0
    {
        uint32_t sb = smem_u;
        load_tile_async(Ah, bm, 0, sb,             tid);
        load_tile_async(Al, bm, 0, sb + TILEB,     tid);
        load_tile_async(Bh, bn, 0, sb + 2*TILEB,   tid);
        load_tile_async(Bl, bn, 0, sb + 3*TILEB,   tid);
        asm volatile("cp.async.commit_group;" ::: "memory");
    }

    // precomputed lane addressing pieces
    const int a_row = wm * 32 + (lane & 15);          // + mb*16
    const int a_hf  = lane >> 4;                      // k half unit
    const int b_row = wn * 64 + (lane & 7) + ((lane >> 4) << 3);  // + np*16
    const int b_hf  = (lane >> 3) & 1;

    for (int c = 0; c < NKC; c++) {
        if (c + 1 < NKC) {
            uint32_t sb = smem_u + ((c + 1) & 1) * STAGEB;
            load_tile_async(Ah, bm, c + 1, sb,             tid);
            load_tile_async(Al, bm, c + 1, sb + TILEB,     tid);
            load_tile_async(Bh, bn, c + 1, sb + 2*TILEB,   tid);
            load_tile_async(Bl, bn, c + 1, sb + 3*TILEB,   tid);
            asm volatile("cp.async.commit_group;" ::: "memory");
            asm volatile("cp.async.wait_group 1;" ::: "memory");
        } else {
            asm volatile("cp.async.wait_group 0;" ::: "memory");
        }
        __syncthreads();

        const uint32_t sA = smem_u + (c & 1) * STAGEB;
        const uint32_t sB = sA + 2*TILEB;

#pragma unroll
        for (int ks = 0; ks < 4; ks++) {
            uint32_t ah[2][4], al[2][4];
#pragma unroll
            for (int mb = 0; mb < 2; mb++) {
                int row = a_row + mb * 16;
                int un  = ks * 2 + a_hf;
                uint32_t off = row * 128 + ((un ^ (row & 7)) * 16);
                ldsm4(sA + off,         ah[mb][0], ah[mb][1], ah[mb][2], ah[mb][3]);
                ldsm4(sA + TILEB + off, al[mb][0], al[mb][1], al[mb][2], al[mb][3]);
            }
#pragma unroll
            for (int np = 0; np < 4; np++) {
                int row = b_row + np * 16;
                int un  = ks * 2 + b_hf;
                uint32_t off = row * 128 + ((un ^ (row & 7)) * 16);
                uint32_t bh0, bh1, bh2, bh3, bl0, bl1, bl2, bl3;
                ldsm4(sB + off,         bh0, bh1, bh2, bh3);
                ldsm4(sB + TILEB + off, bl0, bl1, bl2, bl3);
#pragma unroll
                for (int mb = 0; mb < 2; mb++) {
                    mma16816(acc[mb][np*2+0], ah[mb], bh0, bh1);
                    mma16816(acc[mb][np*2+1], ah[mb], bh2, bh3);
                    mma16816(acc[mb][np*2+0], ah[mb], bl0, bl1);
                    mma16816(acc[mb][np*2+1], ah[mb], bl2, bl3);
                    mma16816(acc[mb][np*2+0], al[mb], bh0, bh1);
                    mma16816(acc[mb][np*2+1], al[mb], bh2, bh3);
                }
            }
        }
        __syncthreads();
    }

    // ---------------- epilogue ----------------
    const int mrow0 = bm + wm * 32 + (lane >> 2);
    const int ncol0 = bn + wn * 64 + (lane & 3) * 2;
#pragma unroll
    for (int mb = 0; mb < 2; mb++) {
#pragma unroll
        for (int n8 = 0; n8 < 8; n8++) {
            int n = ncol0 + n8 * 8;
            int m0 = mrow0 + mb * 16;
            float2 v0 = make_float2(acc[mb][n8][0], acc[mb][n8][1]);
            float2 v1 = make_float2(acc[mb][n8][2], acc[mb][n8][3]);
            if (EPI == 2) {
                *(float2*)(Cout + (size_t)m0 * H_ + n)       = v0;
                *(float2*)(Cout + (size_t)(m0 + 8) * H_ + n) = v1;
            } else if (bn < R_) {
                *(float2*)(g_xr + (size_t)m0 * R_ + n)       = v0;
                *(float2*)(g_xr + (size_t)(m0 + 8) * R_ + n) = v1;
            } else {
                v0.x = 0.5f * v0.x * (1.0f + erff(v0.x * 0.7071067811865476f));
                v0.y = 0.5f * v0.y * (1.0f + erff(v0.y * 0.7071067811865476f));
                v1.x = 0.5f * v1.x * (1.0f + erff(v1.x * 0.7071067811865476f));
                v1.y = 0.5f * v1.y * (1.0f + erff(v1.y * 0.7071067811865476f));
                *(float2*)(g_gy + (size_t)m0 * R_ + (n - R_))       = v0;
                *(float2*)(g_gy + (size_t)(m0 + 8) * R_ + (n - R_)) = v1;
            }
        }
    }
}

// ---------------- causal depthwise conv (CW=4) ------------------------------
__global__ void conv_kernel(const float* __restrict__ conv_w,
                            const float* __restrict__ conv_b)
{
    size_t idx = (size_t)blockIdx.x * blockDim.x + threadIdx.x;
    int r = (int)(idx & (R_ - 1));
    size_t row = idx >> 11;
    int t = (int)(row & (S_ - 1));
    int b = (int)(row >> 12);
    float acc = conv_b[r];
#pragma unroll
    for (int i = 0; i < CW_; i++) {
        int tt = t - (CW_ - 1) + i;
        if (tt >= 0)
            acc += conv_w[i * R_ + r] * g_xr[((size_t)(b * S_ + tt)) * R_ + r];
    }
    g_xc[idx] = acc;
}

// ---------------- block-diag gate GEMMs + RG-LRU elementwise ----------------
__global__ __launch_bounds__(256) void blockdiag_gates(
    const float* __restrict__ igw, const float* __restrict__ igb,
    const float* __restrict__ agw, const float* __restrict__ agb,
    const float* __restrict__ a_param)
{
    __shared__ __align__(16) float Xs[16][128];
    __shared__ __align__(16) float Wi[16][128];
    __shared__ __align__(16) float Wa[16][128];

    const int nb = blockIdx.x;
    const int bm = blockIdx.y * 128;
    const int tid = threadIdx.x;
    const int tx = tid & 15, ty = tid >> 4;
    const int lr = tid >> 2, lc = (tid & 3) << 2;
    const int wr = tid >> 5, wc = (tid & 31) << 2;

    const float* wip = igw + (size_t)nb * BW_ * BW_;
    const float* wap = agw + (size_t)nb * BW_ * BW_;

    float accI[8][8], accA[8][8];
#pragma unroll
    for (int i = 0; i < 8; i++)
#pragma unroll
        for (int j = 0; j < 8; j++) { accI[i][j] = 0.f; accA[i][j] = 0.f; }

    for (int k0 = 0; k0 < BW_; k0 += 16) {
        float4 x0 = *(const float4*)(g_xc + (size_t)(bm + lr)      * R_ + nb*BW_ + k0 + lc);
        float4 x1 = *(const float4*)(g_xc + (size_t)(bm + lr + 64) * R_ + nb*BW_ + k0 + lc);
        float4 wi0 = *(const float4*)(wip + (size_t)(k0 + wr)     * BW_ + wc);
        float4 wi1 = *(const float4*)(wip + (size_t)(k0 + wr + 8) * BW_ + wc);
        float4 wa0 = *(const float4*)(wap + (size_t)(k0 + wr)     * BW_ + wc);
        float4 wa1 = *(const float4*)(wap + (size_t)(k0 + wr + 8) * BW_ + wc);
        __syncthreads();
        Xs[lc+0][lr] = x0.x; Xs[lc+1][lr] = x0.y; Xs[lc+2][lr] = x0.z; Xs[lc+3][lr] = x0.w;
        Xs[lc+0][lr+64] = x1.x; Xs[lc+1][lr+64] = x1.y; Xs[lc+2][lr+64] = x1.z; Xs[lc+3][lr+64] = x1.w;
        *(float4*)(&Wi[wr][wc])     = wi0;
        *(float4*)(&Wi[wr + 8][wc]) = wi1;
        *(float4*)(&Wa[wr][wc])     = wa0;
        *(float4*)(&Wa[wr + 8][wc]) = wa1;
        __syncthreads();

#pragma unroll
        for (int kk = 0; kk < 16; kk++) {
            float ra[8], ri[8], rc[8];
            *(float4*)(&ra[0]) = *(const float4*)(&Xs[kk][ty*4]);
            *(float4*)(&ra[4]) = *(const float4*)(&Xs[kk][64 + ty*4]);
            *(float4*)(&ri[0]) = *(const float4*)(&Wi[kk][tx*4]);
            *(float4*)(&ri[4]) = *(const float4*)(&Wi[kk][64 + tx*4]);
            *(float4*)(&rc[0]) = *(const float4*)(&Wa[kk][tx*4]);
            *(float4*)(&rc[4]) = *(const float4*)(&Wa[kk][64 + tx*4]);
#pragma unroll
            for (int i = 0; i < 8; i++)
#pragma unroll
                for (int j = 0; j < 8; j++) {
                    accI[i][j] += ra[i] * ri[j];
                    accA[i][j] += ra[i] * rc[j];
                }
        }
    }

#pragma unroll
    for (int i = 0; i < 8; i++) {
        int m = bm + ((i < 4) ? (ty*4 + i) : (64 + ty*4 + i - 4));
#pragma unroll
        for (int j = 0; j < 8; j++) {
            int col = (j < 4) ? (tx*4 + j) : (64 + tx*4 + j - 4);
            int r = nb * BW_ + col;
            float xg = accI[i][j] + igb[nb * BW_ + col];
            float ag = accA[i][j] + agb[nb * BW_ + col];
            float ap = a_param[r];
            float sp = (ap > 20.f) ? ap : log1pf(expf(ap));
            float ga = 1.f / (1.f + expf(-ag));
            float la = -8.f * ga * sp;
            float a  = expf(la);
            float mult = sqrtf(-expm1f(2.f * la));
            float gx = 1.f / (1.f + expf(-xg));
            float xv = g_xc[(size_t)m * R_ + r];
            g_av[(size_t)m * R_ + r] = a;
            g_nx[(size_t)m * R_ + r] = xv * gx * mult;
        }
    }
}

// ---------------- chunked linear-recurrence scan ----------------------------
__global__ void scanA()
{
    int r = blockIdx.x * 256 + threadIdx.x;
    int chunk = blockIdx.y;
    int b = blockIdx.z;
    size_t base = ((size_t)(b * S_ + chunk * CHL)) * R_ + r;
    const float* __restrict__ pa = g_av + base;
    const float* __restrict__ px = g_nx + base;
    float A = 1.f, Bv = 0.f;
#pragma unroll 4
    for (int t = 0; t < CHL; t++) {
        float av = pa[(size_t)t * R_];
        float xv = px[(size_t)t * R_];
        Bv = av * Bv + xv;
        A *= av;
    }
    int ch = b * R_ + r;
    g_Asum[ch * NCHUNK + chunk] = A;
    g_Bsum[ch * NCHUNK + chunk] = Bv;
}

__global__ void scanB()
{
    int ch = blockIdx.x * 256 + threadIdx.x;
    float h = 0.f;
#pragma unroll
    for (int c = 0; c < NCHUNK; c++) {
        g_carry[ch * NCHUNK + c] = h;
        h = g_Asum[ch * NCHUNK + c] * h + g_Bsum[ch * NCHUNK + c];
    }
}

__global__ void scanC()
{
    int r = blockIdx.x * 256 + threadIdx.x;
    int chunk = blockIdx.y;
    int b = blockIdx.z;
    size_t base = ((size_t)(b * S_ + chunk * CHL)) * R_ + r;
    const float* __restrict__ pa = g_av + base;
    const float* __restrict__ px = g_nx + base;
    const float* __restrict__ pg = g_gy + base;
    __nv_bfloat16* __restrict__ ph = g_hgh + base;
    __nv_bfloat16* __restrict__ pl = g_hgl + base;
    int ch = b * R_ + r;
    float h = g_carry[ch * NCHUNK + chunk];
#pragma unroll 4
    for (int t = 0; t < CHL; t++) {
        float av = pa[(size_t)t * R_];
        float xv = px[(size_t)t * R_];
        h = av * h + xv;
        float hg = h * pg[(size_t)t * R_];
        __nv_bfloat16 hh, hl;
        split1(hg, hh, hl);
        ph[(size_t)t * R_] = hh;
        pl[(size_t)t * R_] = hl;
    }
}

// ---------------- host launcher ---------------------------------------------
extern "C" void kernel_launch(void* const* d_in, const int* in_sizes, int n_in,
                              void* d_out, int out_size)
{
    const float* x       = (const float*)d_in[0];
    const float* W_xy    = (const float*)d_in[1];
    const float* ig_w    = (const float*)d_in[2];
    const float* ig_b    = (const float*)d_in[3];
    const float* ag_w    = (const float*)d_in[4];
    const float* ag_b    = (const float*)d_in[5];
    const float* a_param = (const float*)d_in[6];
    const float* conv_w  = (const float*)d_in[7];
    const float* conv_b  = (const float*)d_in[8];
    const float* W_resid = (const float*)d_in[9];
    float* out = (float*)d_out;

    cudaFuncSetAttribute(gemm_tc<1>, cudaFuncAttributeMaxDynamicSharedMemorySize, GEMM_SMEM);
    cudaFuncSetAttribute(gemm_tc<2>, cudaFuncAttributeMaxDynamicSharedMemorySize, GEMM_SMEM);

    // 0) split operands to bf16 hi/lo
    split_kernel<0><<<(M_ * H_ / 4) / 256, 256>>>((const float4*)x);
    split_kernel<1><<<(2 * R_ * H_ / 4) / 256, 256>>>((const float4*)W_xy);
    split_kernel<2><<<(H_ * R_ / 4) / 256, 256>>>((const float4*)W_resid);

    // 1) xy = x @ W_xy^T  (HMMA split-bf16; epilogue -> g_xr, gelu -> g_gy)
    {
        dim3 grid(2 * R_ / 128, M_ / 128);   // (32, 64)
        gemm_tc<1><<<grid, 256, GEMM_SMEM>>>(nullptr);
    }
    // 2) causal depthwise conv
    conv_kernel<<<(unsigned)((size_t)M_ * R_ / 256), 256>>>(conv_w, conv_b);
    // 3) block-diag gates + RG-LRU elementwise
    {
        dim3 grid(NB_, M_ / 128);
        blockdiag_gates<<<grid, 256>>>(ig_w, ig_b, ag_w, ag_b, a_param);
    }
    // 4) chunked scan, fused * gelu(y), bf16-split output
    {
        dim3 gA(R_ / 256, NCHUNK, B_);
        scanA<<<gA, 256>>>();
        scanB<<<NCH / 256, 256>>>();
        scanC<<<gA, 256>>>();
    }
    // 5) out = hg @ W_resid^T  (HMMA split-bf16)
    {
        dim3 grid(H_ / 128, M_ / 128);       // (16, 64)
        gemm_tc<2><<<grid, 256, GEMM_SMEM>>>(out);
    }
}

// round 12
// speedup vs baseline: 1.1504x; 1.1489x over previous
#include <cuda_runtime.h>
#include <cuda_bf16.h>
#include <math.h>
#include <stdint.h>

// ---------------- problem constants ----------------
#define B_  2
#define S_  4096
#define H_  2048
#define R_  2048
#define NB_ 16
#define BW_ 128
#define CW_ 4
#define M_  (B_*S_)        // 8192
#define NCHUNK 16
#define CHL (S_/NCHUNK)    // 256
#define NCH (B_*R_)        // 4096
#define KDIM 2048
#define KC  64             // K elements per SMEM chunk
#define NKC (KDIM/KC)      // 32 chunks

// ---------------- scratch (device globals; no allocations allowed) ----------
__device__ float g_xr[(size_t)M_*R_];   // GEMM1 out (xr); later reused as xg_pre
__device__ float g_gy[(size_t)M_*R_];   // gelu(y)
__device__ float g_av[(size_t)M_*R_];   // ag_pre, then a_t
__device__ float g_nx[(size_t)M_*R_];   // norm_x_t
__device__ float g_Asum[NCH*NCHUNK];
__device__ float g_Bsum[NCH*NCHUNK];
__device__ float g_carry[NCH*NCHUNK];

__device__ __nv_bfloat16 g_xh [(size_t)M_*H_];
__device__ __nv_bfloat16 g_xl [(size_t)M_*H_];
__device__ __nv_bfloat16 g_wxyh[(size_t)2*R_*H_];
__device__ __nv_bfloat16 g_wxyl[(size_t)2*R_*H_];
__device__ __nv_bfloat16 g_wrh[(size_t)H_*R_];
__device__ __nv_bfloat16 g_wrl[(size_t)H_*R_];
__device__ __nv_bfloat16 g_hgh[(size_t)M_*R_];
__device__ __nv_bfloat16 g_hgl[(size_t)M_*R_];
__device__ __nv_bfloat16 g_xch[(size_t)M_*R_];   // conv out hi
__device__ __nv_bfloat16 g_xcl[(size_t)M_*R_];   // conv out lo
__device__ __nv_bfloat16 g_gwh[(size_t)NB_*256*128]; // gate W [nb][n=256][k=128] hi
__device__ __nv_bfloat16 g_gwl[(size_t)NB_*256*128]; // lo

// ---------------- helpers ----------------------------------------------------
__device__ __forceinline__ uint32_t smem_to_u32(const void* p) {
    uint32_t a;
    asm("{ .reg .u64 t; cvta.to.shared.u64 t, %1; cvt.u32.u64 %0, t; }"
        : "=r"(a) : "l"(p));
    return a;
}

__device__ __forceinline__ void ldsm4(uint32_t addr,
    uint32_t& r0, uint32_t& r1, uint32_t& r2, uint32_t& r3)
{
    asm volatile("ldmatrix.sync.aligned.m8n8.x4.shared.b16 {%0,%1,%2,%3}, [%4];"
        : "=r"(r0), "=r"(r1), "=r"(r2), "=r"(r3) : "r"(addr));
}

__device__ __forceinline__ void mma16816(float* c,
    const uint32_t* a, uint32_t b0, uint32_t b1)
{
    asm volatile(
        "mma.sync.aligned.m16n8k16.row.col.f32.bf16.bf16.f32 "
        "{%0,%1,%2,%3}, {%4,%5,%6,%7}, {%8,%9}, {%0,%1,%2,%3};"
        : "+f"(c[0]), "+f"(c[1]), "+f"(c[2]), "+f"(c[3])
        : "r"(a[0]), "r"(a[1]), "r"(a[2]), "r"(a[3]), "r"(b0), "r"(b1));
}

__device__ __forceinline__ void split1(float v, __nv_bfloat16& h, __nv_bfloat16& l)
{
    h = __float2bfloat16(v);
    l = __float2bfloat16(v - __bfloat162float(h));
}

// ---------------- fp32 -> (bf16 hi, bf16 lo) split --------------------------
template <int DST>
__global__ void split_kernel(const float4* __restrict__ src)
{
    int i = blockIdx.x * 256 + threadIdx.x;
    float4 v = src[i];
    __nv_bfloat16 h0, h1, h2, h3, l0, l1, l2, l3;
    split1(v.x, h0, l0); split1(v.y, h1, l1);
    split1(v.z, h2, l2); split1(v.w, h3, l3);
    uint2 hv, lv;
    hv.x = (uint32_t)__bfloat16_as_ushort(h0) | ((uint32_t)__bfloat16_as_ushort(h1) << 16);
    hv.y = (uint32_t)__bfloat16_as_ushort(h2) | ((uint32_t)__bfloat16_as_ushort(h3) << 16);
    lv.x = (uint32_t)__bfloat16_as_ushort(l0) | ((uint32_t)__bfloat16_as_ushort(l1) << 16);
    lv.y = (uint32_t)__bfloat16_as_ushort(l2) | ((uint32_t)__bfloat16_as_ushort(l3) << 16);
    __nv_bfloat16 *hp, *lp;
    if (DST == 0)      { hp = g_xh;   lp = g_xl;   }
    else if (DST == 1) { hp = g_wxyh; lp = g_wxyl; }
    else               { hp = g_wrh;  lp = g_wrl;  }
    *(uint2*)(hp + 4ull * i) = hv;
    *(uint2*)(lp + 4ull * i) = lv;
}

// transpose + split gate weights: out[nb][j][i] = ig_w[nb][i][j] (rows 0..127)
//                                 out[nb][128+j][i] = ag_w[nb][i][j]
__global__ void split_gatew(const float* __restrict__ igw,
                            const float* __restrict__ agw)
{
    int idx = blockIdx.x * 256 + threadIdx.x;   // over 16*128*128
    int nb = idx >> 14;
    int i  = (idx >> 7) & 127;
    int j  = idx & 127;
    float iv = igw[idx];
    float av = agw[idx];
    __nv_bfloat16 ih, il, ah, al;
    split1(iv, ih, il);
    split1(av, ah, al);
    size_t d1 = (size_t)nb * 32768 + (size_t)j * 128 + i;
    size_t d2 = d1 + 128 * 128;
    g_gwh[d1] = ih; g_gwl[d1] = il;
    g_gwh[d2] = ah; g_gwl[d2] = al;
}

// ---------------- HMMA split-bf16 GEMM (TN) ----------------------------------
// Tile 128x128, 8 warps (4x2), warp tile 32x64. BK=64, 3-stage cp.async.
#define TILEB   16384
#define STAGEB  (4*TILEB)
#define GEMM_SMEM (3*STAGEB)   // 196608

__device__ __forceinline__ void load_tile_async(
    const __nv_bfloat16* __restrict__ g, int row0, int kc,
    uint32_t sdst, int tid)
{
#pragma unroll
    for (int i = 0; i < 4; i++) {
        int u = i * 256 + tid;
        int row = u >> 3;
        int un  = u & 7;
        const __nv_bfloat16* src = g + (size_t)(row0 + row) * KDIM + kc * KC + un * 8;
        uint32_t dst = sdst + row * 128 + ((un ^ (row & 7)) * 16);
        asm volatile("cp.async.cg.shared.global [%0], [%1], 16;"
            :: "r"(dst), "l"(src) : "memory");
    }
}

template <int EPI>
__global__ __launch_bounds__(256) void gemm_tc(float* __restrict__ Cout)
{
    extern __shared__ char smem[];
    const uint32_t smem_u = smem_to_u32(smem);
    const int tid  = threadIdx.x;
    const int lane = tid & 31;
    const int wm   = (tid >> 5) & 3;
    const int wn   = tid >> 7;
    const int bm = blockIdx.y * 128;
    const int bn = blockIdx.x * 128;

    const __nv_bfloat16 *Ah, *Al, *Bh, *Bl;
    if (EPI == 1) { Ah = g_xh;  Al = g_xl;  Bh = g_wxyh; Bl = g_wxyl; }
    else          { Ah = g_hgh; Al = g_hgl; Bh = g_wrh;  Bl = g_wrl;  }

    float acc[2][8][4];
#pragma unroll
    for (int mb = 0; mb < 2; mb++)
#pragma unroll
        for (int n8 = 0; n8 < 8; n8++)
#pragma unroll
            for (int q = 0; q < 4; q++) acc[mb][n8][q] = 0.f;

    // prologue: chunks 0,1 -> stages 0,1
#pragma unroll
    for (int p = 0; p < 2; p++) {
        uint32_t sb = smem_u + p * STAGEB;
        load_tile_async(Ah, bm, p, sb,             tid);
        load_tile_async(Al, bm, p, sb + TILEB,     tid);
        load_tile_async(Bh, bn, p, sb + 2*TILEB,   tid);
        load_tile_async(Bl, bn, p, sb + 3*TILEB,   tid);
        asm volatile("cp.async.commit_group;" ::: "memory");
    }

    const int a_row = wm * 32 + (lane & 15);
    const int a_hf  = lane >> 4;
    const int b_row = wn * 64 + (lane & 7) + ((lane >> 4) << 3);
    const int b_hf  = (lane >> 3) & 1;

    int stage = 0;
    for (int c = 0; c < NKC; c++) {
        if (c + 2 < NKC) {
            int s2 = stage + 2; if (s2 >= 3) s2 -= 3;
            uint32_t sb = smem_u + s2 * STAGEB;
            load_tile_async(Ah, bm, c + 2, sb,             tid);
            load_tile_async(Al, bm, c + 2, sb + TILEB,     tid);
            load_tile_async(Bh, bn, c + 2, sb + 2*TILEB,   tid);
            load_tile_async(Bl, bn, c + 2, sb + 3*TILEB,   tid);
            asm volatile("cp.async.commit_group;" ::: "memory");
            asm volatile("cp.async.wait_group 2;" ::: "memory");
        } else if (c + 1 < NKC) {
            asm volatile("cp.async.wait_group 1;" ::: "memory");
        } else {
            asm volatile("cp.async.wait_group 0;" ::: "memory");
        }
        __syncthreads();

        const uint32_t sA = smem_u + stage * STAGEB;
        const uint32_t sB = sA + 2*TILEB;

        // A-fragment register double buffer across ks
        uint32_t ahb[2][2][4], alb[2][2][4];
#pragma unroll
        for (int mb = 0; mb < 2; mb++) {
            int row = a_row + mb * 16;
            uint32_t off = row * 128 + ((a_hf ^ (row & 7)) * 16);
            ldsm4(sA + off,         ahb[0][mb][0], ahb[0][mb][1], ahb[0][mb][2], ahb[0][mb][3]);
            ldsm4(sA + TILEB + off, alb[0][mb][0], alb[0][mb][1], alb[0][mb][2], alb[0][mb][3]);
        }

#pragma unroll
        for (int ks = 0; ks < 4; ks++) {
            const int cur = ks & 1;
            if (ks < 3) {
#pragma unroll
                for (int mb = 0; mb < 2; mb++) {
                    int row = a_row + mb * 16;
                    int un  = (ks + 1) * 2 + a_hf;
                    uint32_t off = row * 128 + ((un ^ (row & 7)) * 16);
                    ldsm4(sA + off,         ahb[cur^1][mb][0], ahb[cur^1][mb][1],
                                            ahb[cur^1][mb][2], ahb[cur^1][mb][3]);
                    ldsm4(sA + TILEB + off, alb[cur^1][mb][0], alb[cur^1][mb][1],
                                            alb[cur^1][mb][2], alb[cur^1][mb][3]);
                }
            }
#pragma unroll
            for (int np = 0; np < 4; np++) {
                int row = b_row + np * 16;
                int un  = ks * 2 + b_hf;
                uint32_t off = row * 128 + ((un ^ (row & 7)) * 16);
                uint32_t bh0, bh1, bh2, bh3, bl0, bl1, bl2, bl3;
                ldsm4(sB + off,         bh0, bh1, bh2, bh3);
                ldsm4(sB + TILEB + off, bl0, bl1, bl2, bl3);
#pragma unroll
                for (int mb = 0; mb < 2; mb++) {
                    mma16816(acc[mb][np*2+0], ahb[cur][mb], bh0, bh1);
                    mma16816(acc[mb][np*2+1], ahb[cur][mb], bh2, bh3);
                    mma16816(acc[mb][np*2+0], ahb[cur][mb], bl0, bl1);
                    mma16816(acc[mb][np*2+1], ahb[cur][mb], bl2, bl3);
                    mma16816(acc[mb][np*2+0], alb[cur][mb], bh0, bh1);
                    mma16816(acc[mb][np*2+1], alb[cur][mb], bh2, bh3);
                }
            }
        }
        __syncthreads();
        stage++; if (stage >= 3) stage = 0;
    }

    // ---------------- epilogue ----------------
    const int mrow0 = bm + wm * 32 + (lane >> 2);
    const int ncol0 = bn + wn * 64 + (lane & 3) * 2;
#pragma unroll
    for (int mb = 0; mb < 2; mb++) {
#pragma unroll
        for (int n8 = 0; n8 < 8; n8++) {
            int n = ncol0 + n8 * 8;
            int m0 = mrow0 + mb * 16;
            float2 v0 = make_float2(acc[mb][n8][0], acc[mb][n8][1]);
            float2 v1 = make_float2(acc[mb][n8][2], acc[mb][n8][3]);
            if (EPI == 2) {
                *(float2*)(Cout + (size_t)m0 * H_ + n)       = v0;
                *(float2*)(Cout + (size_t)(m0 + 8) * H_ + n) = v1;
            } else if (bn < R_) {
                *(float2*)(g_xr + (size_t)m0 * R_ + n)       = v0;
                *(float2*)(g_xr + (size_t)(m0 + 8) * R_ + n) = v1;
            } else {
                v0.x = 0.5f * v0.x * (1.0f + erff(v0.x * 0.7071067811865476f));
                v0.y = 0.5f * v0.y * (1.0f + erff(v0.y * 0.7071067811865476f));
                v1.x = 0.5f * v1.x * (1.0f + erff(v1.x * 0.7071067811865476f));
                v1.y = 0.5f * v1.y * (1.0f + erff(v1.y * 0.7071067811865476f));
                *(float2*)(g_gy + (size_t)m0 * R_ + (n - R_))       = v0;
                *(float2*)(g_gy + (size_t)(m0 + 8) * R_ + (n - R_)) = v1;
            }
        }
    }
}

// ---------------- causal depthwise conv (CW=4) -> bf16 split -----------------
__global__ void conv_kernel(const float* __restrict__ conv_w,
                            const float* __restrict__ conv_b)
{
    size_t idx = (size_t)blockIdx.x * blockDim.x + threadIdx.x;
    int r = (int)(idx & (R_ - 1));
    size_t row = idx >> 11;
    int t = (int)(row & (S_ - 1));
    int b = (int)(row >> 12);
    float acc = conv_b[r];
#pragma unroll
    for (int i = 0; i < CW_; i++) {
        int tt = t - (CW_ - 1) + i;
        if (tt >= 0)
            acc += conv_w[i * R_ + r] * g_xr[((size_t)(b * S_ + tt)) * R_ + r];
    }
    __nv_bfloat16 h, l;
    split1(acc, h, l);
    g_xch[idx] = h;
    g_xcl[idx] = l;
}

// ---------------- block-diag gate GEMMs on HMMA ------------------------------
// grid (NB_, M_/128), 512 threads = 16 warps (4 m-rows x 4 n-cols over N=256).
// B = concat(ig_w^T, ag_w^T)[nb] : [256, 128]. Output raw pre-activations:
// cols 0..127 -> g_xr (xg_pre), cols 128..255 -> g_av (ag_pre).
#define GW_SMEM (196608)   // XH 32K | XL 32K | WH 64K | WL 64K

__global__ __launch_bounds__(512) void gates_mma()
{
    extern __shared__ char smem[];
    const uint32_t smem_u = smem_to_u32(smem);
    const int tid  = threadIdx.x;
    const int lane = tid & 31;
    const int wid  = tid >> 5;
    const int wm   = wid & 3;
    const int wn   = wid >> 2;          // 0..3 over N=256
    const int nb   = blockIdx.x;
    const int bm   = blockIdx.y * 128;

    // load X (hi/lo) 2 chunks of [128 x 64] each
#pragma unroll
    for (int hl = 0; hl < 2; hl++) {
        const __nv_bfloat16* src0 = hl ? g_xcl : g_xch;
#pragma unroll
        for (int c2 = 0; c2 < 2; c2++) {
#pragma unroll
            for (int i = 0; i < 2; i++) {
                int u = i * 512 + tid;      // 0..1023
                int row = u >> 3;
                int un  = u & 7;
                const __nv_bfloat16* src =
                    src0 + (size_t)(bm + row) * R_ + nb * 128 + c2 * 64 + un * 8;
                uint32_t dst = smem_u + hl * 32768 + c2 * 16384
                             + row * 128 + ((un ^ (row & 7)) * 16);
                asm volatile("cp.async.cg.shared.global [%0], [%1], 16;"
                    :: "r"(dst), "l"(src) : "memory");
            }
        }
    }
    // load W (hi/lo) 2 chunks of [256 x 64]
#pragma unroll
    for (int hl = 0; hl < 2; hl++) {
        const __nv_bfloat16* src0 = (hl ? g_gwl : g_gwh) + (size_t)nb * 32768;
#pragma unroll
        for (int c2 = 0; c2 < 2; c2++) {
#pragma unroll
            for (int i = 0; i < 4; i++) {
                int u = i * 512 + tid;      // 0..2047
                int row = u >> 3;           // 0..255
                int un  = u & 7;
                const __nv_bfloat16* src = src0 + (size_t)row * 128 + c2 * 64 + un * 8;
                uint32_t dst = smem_u + 65536 + hl * 65536 + c2 * 32768
                             + row * 128 + ((un ^ (row & 7)) * 16);
                asm volatile("cp.async.cg.shared.global [%0], [%1], 16;"
                    :: "r"(dst), "l"(src) : "memory");
            }
        }
    }
    asm volatile("cp.async.commit_group;" ::: "memory");
    asm volatile("cp.async.wait_group 0;" ::: "memory");
    __syncthreads();

    const int a_row = wm * 32 + (lane & 15);
    const int a_hf  = lane >> 4;
    const int b_row = wn * 64 + (lane & 7) + ((lane >> 4) << 3);
    const int b_hf  = (lane >> 3) & 1;

    float acc[2][8][4];
#pragma unroll
    for (int mb = 0; mb < 2; mb++)
#pragma unroll
        for (int n8 = 0; n8 < 8; n8++)
#pragma unroll
            for (int q = 0; q < 4; q++) acc[mb][n8][q] = 0.f;

#pragma unroll
    for (int c2 = 0; c2 < 2; c2++) {
        const uint32_t sXh = smem_u + c2 * 16384;
        const uint32_t sXl = smem_u + 32768 + c2 * 16384;
        const uint32_t sWh = smem_u + 65536  + c2 * 32768;
        const uint32_t sWl = smem_u + 131072 + c2 * 32768;
#pragma unroll
        for (int ks = 0; ks < 4; ks++) {
            uint32_t ah[2][4], al[2][4];
#pragma unroll
            for (int mb = 0; mb < 2; mb++) {
                int row = a_row + mb * 16;
                int un  = ks * 2 + a_hf;
                uint32_t off = row * 128 + ((un ^ (row & 7)) * 16);
                ldsm4(sXh + off, ah[mb][0], ah[mb][1], ah[mb][2], ah[mb][3]);
                ldsm4(sXl + off, al[mb][0], al[mb][1], al[mb][2], al[mb][3]);
            }
#pragma unroll
            for (int np = 0; np < 4; np++) {
                int row = b_row + np * 16;
                int un  = ks * 2 + b_hf;
                uint32_t off = row * 128 + ((un ^ (row & 7)) * 16);
                uint32_t bh0, bh1, bh2, bh3, bl0, bl1, bl2, bl3;
                ldsm4(sWh + off, bh0, bh1, bh2, bh3);
                ldsm4(sWl + off, bl0, bl1, bl2, bl3);
#pragma unroll
                for (int mb = 0; mb < 2; mb++) {
                    mma16816(acc[mb][np*2+0], ah[mb], bh0, bh1);
                    mma16816(acc[mb][np*2+1], ah[mb], bh2, bh3);
                    mma16816(acc[mb][np*2+0], ah[mb], bl0, bl1);
                    mma16816(acc[mb][np*2+1], ah[mb], bl2, bl3);
                    mma16816(acc[mb][np*2+0], al[mb], bh0, bh1);
                    mma16816(acc[mb][np*2+1], al[mb], bh2, bh3);
                }
            }
        }
    }

    // epilogue: cols<128 -> xg_pre (g_xr), cols>=128 -> ag_pre (g_av)
    const int mrow0 = bm + wm * 32 + (lane >> 2);
    const int col0  = wn * 64 + (lane & 3) * 2;   // 0..255
    float* basep = (col0 < 128) ? g_xr : g_av;
#pragma unroll
    for (int mb = 0; mb < 2; mb++) {
#pragma unroll
        for (int n8 = 0; n8 < 8; n8++) {
            int colr = (col0 & 127) + n8 * 8;
            int m0 = mrow0 + mb * 16;
            size_t d0 = (size_t)m0 * R_ + nb * 128 + colr;
            float2 v0 = make_float2(acc[mb][n8][0], acc[mb][n8][1]);
            float2 v1 = make_float2(acc[mb][n8][2], acc[mb][n8][3]);
            *(float2*)(basep + d0)            = v0;
            *(float2*)(basep + d0 + 8ull*R_)  = v1;
        }
    }
}

// ---------------- gate nonlinearity (elementwise) ----------------------------
__global__ void gates_elem(const float* __restrict__ igb,
                           const float* __restrict__ agb,
                           const float* __restrict__ a_param)
{
    size_t idx = (size_t)blockIdx.x * blockDim.x + threadIdx.x;
    int r = (int)(idx & (R_ - 1));
    float xg = g_xr[idx] + igb[r];
    float ag = g_av[idx] + agb[r];
    float xv = __bfloat162float(g_xch[idx]) + __bfloat162float(g_xcl[idx]);
    float ap = a_param[r];
    float sp = (ap > 20.f) ? ap : log1pf(expf(ap));
    float ga = 1.f / (1.f + expf(-ag));
    float la = -8.f * ga * sp;
    float a  = expf(la);
    float mult = sqrtf(-expm1f(2.f * la));
    float gx = 1.f / (1.f + expf(-xg));
    g_av[idx] = a;
    g_nx[idx] = xv * gx * mult;
}

// ---------------- chunked linear-recurrence scan ----------------------------
__global__ void scanA()
{
    int r = blockIdx.x * 256 + threadIdx.x;
    int chunk = blockIdx.y;
    int b = blockIdx.z;
    size_t base = ((size_t)(b * S_ + chunk * CHL)) * R_ + r;
    const float* __restrict__ pa = g_av + base;
    const float* __restrict__ px = g_nx + base;
    float A = 1.f, Bv = 0.f;
#pragma unroll 4
    for (int t = 0; t < CHL; t++) {
        float av = pa[(size_t)t * R_];
        float xv = px[(size_t)t * R_];
        Bv = av * Bv + xv;
        A *= av;
    }
    int ch = b * R_ + r;
    g_Asum[ch * NCHUNK + chunk] = A;
    g_Bsum[ch * NCHUNK + chunk] = Bv;
}

__global__ void scanB()
{
    int ch = blockIdx.x * 256 + threadIdx.x;
    float h = 0.f;
#pragma unroll
    for (int c = 0; c < NCHUNK; c++) {
        g_carry[ch * NCHUNK + c] = h;
        h = g_Asum[ch * NCHUNK + c] * h + g_Bsum[ch * NCHUNK + c];
    }
}

__global__ void scanC()
{
    int r = blockIdx.x * 256 + threadIdx.x;
    int chunk = blockIdx.y;
    int b = blockIdx.z;
    size_t base = ((size_t)(b * S_ + chunk * CHL)) * R_ + r;
    const float* __restrict__ pa = g_av + base;
    const float* __restrict__ px = g_nx + base;
    const float* __restrict__ pg = g_gy + base;
    __nv_bfloat16* __restrict__ ph = g_hgh + base;
    __nv_bfloat16* __restrict__ pl = g_hgl + base;
    int ch = b * R_ + r;
    float h = g_carry[ch * NCHUNK + chunk];
#pragma unroll 4
    for (int t = 0; t < CHL; t++) {
        float av = pa[(size_t)t * R_];
        float xv = px[(size_t)t * R_];
        h = av * h + xv;
        float hg = h * pg[(size_t)t * R_];
        __nv_bfloat16 hh, hl;
        split1(hg, hh, hl);
        ph[(size_t)t * R_] = hh;
        pl[(size_t)t * R_] = hl;
    }
}

// ---------------- host launcher ---------------------------------------------
extern "C" void kernel_launch(void* const* d_in, const int* in_sizes, int n_in,
                              void* d_out, int out_size)
{
    const float* x       = (const float*)d_in[0];
    const float* W_xy    = (const float*)d_in[1];
    const float* ig_w    = (const float*)d_in[2];
    const float* ig_b    = (const float*)d_in[3];
    const float* ag_w    = (const float*)d_in[4];
    const float* ag_b    = (const float*)d_in[5];
    const float* a_param = (const float*)d_in[6];
    const float* conv_w  = (const float*)d_in[7];
    const float* conv_b  = (const float*)d_in[8];
    const float* W_resid = (const float*)d_in[9];
    float* out = (float*)d_out;

    cudaFuncSetAttribute(gemm_tc<1>, cudaFuncAttributeMaxDynamicSharedMemorySize, GEMM_SMEM);
    cudaFuncSetAttribute(gemm_tc<2>, cudaFuncAttributeMaxDynamicSharedMemorySize, GEMM_SMEM);
    cudaFuncSetAttribute(gates_mma,  cudaFuncAttributeMaxDynamicSharedMemorySize, GW_SMEM);

    // 0) splits
    split_kernel<0><<<(M_ * H_ / 4) / 256, 256>>>((const float4*)x);
    split_kernel<1><<<(2 * R_ * H_ / 4) / 256, 256>>>((const float4*)W_xy);
    split_kernel<2><<<(H_ * R_ / 4) / 256, 256>>>((const float4*)W_resid);
    split_gatew<<<(NB_ * BW_ * BW_) / 256, 256>>>(ig_w, ag_w);

    // 1) xy = x @ W_xy^T  (HMMA split-bf16; epilogue -> g_xr, gelu -> g_gy)
    {
        dim3 grid(2 * R_ / 128, M_ / 128);   // (32, 64)
        gemm_tc<1><<<grid, 256, GEMM_SMEM>>>(nullptr);
    }
    // 2) causal depthwise conv -> bf16 split xc
    conv_kernel<<<(unsigned)((size_t)M_ * R_ / 256), 256>>>(conv_w, conv_b);
    // 3) block-diag gate GEMMs on HMMA + elementwise nonlinearity
    {
        dim3 grid(NB_, M_ / 128);
        gates_mma<<<grid, 512, GW_SMEM>>>();
        gates_elem<<<(unsigned)((size_t)M_ * R_ / 256), 256>>>(ig_b, ag_b, a_param);
    }
    // 4) chunked scan, fused * gelu(y), bf16-split output
    {
        dim3 gA(R_ / 256, NCHUNK, B_);
        scanA<<<gA, 256>>>();
        scanB<<<NCH / 256, 256>>>();
        scanC<<<gA, 256>>>();
    }
    // 5) out = hg @ W_resid^T  (HMMA split-bf16)
    {
        dim3 grid(H_ / 128, M_ / 128);       // (16, 64)
        gemm_tc<2><<<grid, 256, GEMM_SMEM>>>(out);
    }
}

// round 16
// speedup vs baseline: 1.8532x; 1.6109x over previous
#include <cuda_runtime.h>
#include <cuda_fp16.h>
#include <math.h>
#include <stdint.h>

// ---------------- problem constants ----------------
#define B_  2
#define S_  4096
#define H_  2048
#define R_  2048
#define NB_ 16
#define BW_ 128
#define CW_ 4
#define M_  (B_*S_)        // 8192
#define NCHUNK 32
#define CHL (S_/NCHUNK)    // 128
#define NCH (B_*R_)        // 4096
#define KDIM 2048
#define KC  64             // K elements per SMEM chunk
#define NKC (KDIM/KC)      // 32 chunks

// ---------------- scratch (device globals; no allocations allowed) ----------
__device__ float g_xr[(size_t)M_*R_];   // GEMM1 out (xr), feeds conv
__device__ float g_gy[(size_t)M_*R_];   // gelu(y)
__device__ float g_av[(size_t)M_*R_];   // a_t
__device__ float g_nx[(size_t)M_*R_];   // norm_x_t
__device__ float g_Asum[NCH*NCHUNK];
__device__ float g_Bsum[NCH*NCHUNK];
__device__ float g_carry[NCH*NCHUNK];
__device__ float g_sp[R_];              // softplus(a_param), per channel

__device__ __half g_xh [(size_t)M_*H_];     // x hi (fp16 split)
__device__ __half g_xl [(size_t)M_*H_];     // x lo
__device__ __half g_wxyh[(size_t)2*R_*H_];  // W_xy fp16
__device__ __half g_wrh[(size_t)H_*R_];     // W_resid fp16
__device__ __half g_hgh[(size_t)M_*R_];     // h*gelu(y) fp16
__device__ __half g_xch[(size_t)M_*R_];     // conv out fp16
__device__ __half g_gwh[(size_t)NB_*256*128]; // gate W [nb][n=256][k=128] fp16

// ---------------- helpers ----------------------------------------------------
__device__ __forceinline__ uint32_t smem_to_u32(const void* p) {
    uint32_t a;
    asm("{ .reg .u64 t; cvta.to.shared.u64 t, %1; cvt.u32.u64 %0, t; }"
        : "=r"(a) : "l"(p));
    return a;
}

__device__ __forceinline__ void ldsm4(uint32_t addr,
    uint32_t& r0, uint32_t& r1, uint32_t& r2, uint32_t& r3)
{
    asm volatile("ldmatrix.sync.aligned.m8n8.x4.shared.b16 {%0,%1,%2,%3}, [%4];"
        : "=r"(r0), "=r"(r1), "=r"(r2), "=r"(r3) : "r"(addr));
}

__device__ __forceinline__ void mma16816(float* c,
    const uint32_t* a, uint32_t b0, uint32_t b1)
{
    asm volatile(
        "mma.sync.aligned.m16n8k16.row.col.f32.f16.f16.f32 "
        "{%0,%1,%2,%3}, {%4,%5,%6,%7}, {%8,%9}, {%0,%1,%2,%3};"
        : "+f"(c[0]), "+f"(c[1]), "+f"(c[2]), "+f"(c[3])
        : "r"(a[0]), "r"(a[1]), "r"(a[2]), "r"(a[3]), "r"(b0), "r"(b1));
}

// ---------------- conversion kernels ----------------------------------------
// x -> fp16 hi/lo split (A operand of GEMM1 carries 22 mantissa bits)
__global__ void split_x(const float4* __restrict__ src)
{
    int i = blockIdx.x * 256 + threadIdx.x;
    float4 v = src[i];
    __half h[4], l[4];
    h[0] = __float2half_rn(v.x); l[0] = __float2half_rn(v.x - __half2float(h[0]));
    h[1] = __float2half_rn(v.y); l[1] = __float2half_rn(v.y - __half2float(h[1]));
    h[2] = __float2half_rn(v.z); l[2] = __float2half_rn(v.z - __half2float(h[2]));
    h[3] = __float2half_rn(v.w); l[3] = __float2half_rn(v.w - __half2float(h[3]));
    *(uint2*)(g_xh + 4ull * i) = *(uint2*)h;
    *(uint2*)(g_xl + 4ull * i) = *(uint2*)l;
}

// plain fp32 -> fp16 convert. DST: 0 = W_xy, 1 = W_resid
template <int DST>
__global__ void cvt_half(const float4* __restrict__ src)
{
    int i = blockIdx.x * 256 + threadIdx.x;
    float4 v = src[i];
    __half h[4];
    h[0] = __float2half_rn(v.x); h[1] = __float2half_rn(v.y);
    h[2] = __float2half_rn(v.z); h[3] = __float2half_rn(v.w);
    __half* dst = (DST == 0) ? g_wxyh : g_wrh;
    *(uint2*)(dst + 4ull * i) = *(uint2*)h;
}

// transpose + convert gate weights: [nb][j][i] = ig_w[nb][i][j] rows 0..127,
// rows 128..255 = ag_w^T
__global__ void split_gatew(const float* __restrict__ igw,
                            const float* __restrict__ agw)
{
    int idx = blockIdx.x * 256 + threadIdx.x;
    int nb = idx >> 14;
    int i  = (idx >> 7) & 127;
    int j  = idx & 127;
    size_t d1 = (size_t)nb * 32768 + (size_t)j * 128 + i;
    g_gwh[d1]             = __float2half_rn(igw[idx]);
    g_gwh[d1 + 128 * 128] = __float2half_rn(agw[idx]);
}

__global__ void prep_sp(const float* __restrict__ ap)
{
    int r = blockIdx.x * 256 + threadIdx.x;
    float a = ap[r];
    g_sp[r] = (a > 20.f) ? a : log1pf(expf(a));
}

// ---------------- fp16 HMMA GEMM (TN) ----------------------------------------
// C[m,n] = sum_k A[m,k]*B[n,k]; 128x128 tile, 8 warps (4x2), warp 32x64.
// EPI 1: A = x split (hi+lo, 2 products), B = W_xy fp16. -> g_xr / gelu g_gy
// EPI 2: A = hg fp16 (1 product), B = W_resid fp16.      -> Cout
#define TILEB   16384

__device__ __forceinline__ void load_tile_async(
    const __half* __restrict__ g, int row0, int kc, uint32_t sdst, int tid)
{
#pragma unroll
    for (int i = 0; i < 4; i++) {
        int u = i * 256 + tid;
        int row = u >> 3;
        int un  = u & 7;
        const __half* src = g + (size_t)(row0 + row) * KDIM + kc * KC + un * 8;
        uint32_t dst = sdst + row * 128 + ((un ^ (row & 7)) * 16);
        asm volatile("cp.async.cg.shared.global [%0], [%1], 16;"
            :: "r"(dst), "l"(src) : "memory");
    }
}

template <int EPI>
__global__ __launch_bounds__(256) void gemm_tc(float* __restrict__ Cout)
{
    constexpr int NT = (EPI == 1) ? 3 : 2;        // tiles per stage
    constexpr int STAGEB = NT * TILEB;
    extern __shared__ char smem[];
    const uint32_t smem_u = smem_to_u32(smem);
    const int tid  = threadIdx.x;
    const int lane = tid & 31;
    const int wm   = (tid >> 5) & 3;
    const int wn   = tid >> 7;
    const int bm = blockIdx.y * 128;
    const int bn = blockIdx.x * 128;

    const __half *Ah, *Al, *Bt;
    if (EPI == 1) { Ah = g_xh;  Al = g_xl; Bt = g_wxyh; }
    else          { Ah = g_hgh; Al = nullptr; Bt = g_wrh; }

    float acc[2][8][4];
#pragma unroll
    for (int mb = 0; mb < 2; mb++)
#pragma unroll
        for (int n8 = 0; n8 < 8; n8++)
#pragma unroll
            for (int q = 0; q < 4; q++) acc[mb][n8][q] = 0.f;

    // prologue: chunks 0,1
#pragma unroll
    for (int p = 0; p < 2; p++) {
        uint32_t sb = smem_u + p * STAGEB;
        load_tile_async(Ah, bm, p, sb, tid);
        if (EPI == 1) load_tile_async(Al, bm, p, sb + TILEB, tid);
        load_tile_async(Bt, bn, p, sb + (NT - 1) * TILEB, tid);
        asm volatile("cp.async.commit_group;" ::: "memory");
    }

    const int a_row = wm * 32 + (lane & 15);
    const int a_hf  = lane >> 4;
    const int b_row = wn * 64 + (lane & 7) + ((lane >> 4) << 3);
    const int b_hf  = (lane >> 3) & 1;

    int stage = 0;
    for (int c = 0; c < NKC; c++) {
        if (c + 2 < NKC) {
            int s2 = stage + 2; if (s2 >= 3) s2 -= 3;
            uint32_t sb = smem_u + s2 * STAGEB;
            load_tile_async(Ah, bm, c + 2, sb, tid);
            if (EPI == 1) load_tile_async(Al, bm, c + 2, sb + TILEB, tid);
            load_tile_async(Bt, bn, c + 2, sb + (NT - 1) * TILEB, tid);
            asm volatile("cp.async.commit_group;" ::: "memory");
            asm volatile("cp.async.wait_group 2;" ::: "memory");
        } else if (c + 1 < NKC) {
            asm volatile("cp.async.wait_group 1;" ::: "memory");
        } else {
            asm volatile("cp.async.wait_group 0;" ::: "memory");
        }
        __syncthreads();

        const uint32_t sA = smem_u + stage * STAGEB;
        const uint32_t sB = sA + (NT - 1) * TILEB;

        uint32_t ahb[2][2][4], alb[2][2][4];
#pragma unroll
        for (int mb = 0; mb < 2; mb++) {
            int row = a_row + mb * 16;
            uint32_t off = row * 128 + ((a_hf ^ (row & 7)) * 16);
            ldsm4(sA + off, ahb[0][mb][0], ahb[0][mb][1], ahb[0][mb][2], ahb[0][mb][3]);
            if (EPI == 1)
                ldsm4(sA + TILEB + off, alb[0][mb][0], alb[0][mb][1], alb[0][mb][2], alb[0][mb][3]);
        }

#pragma unroll
        for (int ks = 0; ks < 4; ks++) {
            const int cur = ks & 1;
            if (ks < 3) {
#pragma unroll
                for (int mb = 0; mb < 2; mb++) {
                    int row = a_row + mb * 16;
                    int un  = (ks + 1) * 2 + a_hf;
                    uint32_t off = row * 128 + ((un ^ (row & 7)) * 16);
                    ldsm4(sA + off, ahb[cur^1][mb][0], ahb[cur^1][mb][1],
                                    ahb[cur^1][mb][2], ahb[cur^1][mb][3]);
                    if (EPI == 1)
                        ldsm4(sA + TILEB + off, alb[cur^1][mb][0], alb[cur^1][mb][1],
                                                alb[cur^1][mb][2], alb[cur^1][mb][3]);
                }
            }
#pragma unroll
            for (int np = 0; np < 4; np++) {
                int row = b_row + np * 16;
                int un  = ks * 2 + b_hf;
                uint32_t off = row * 128 + ((un ^ (row & 7)) * 16);
                uint32_t b0, b1, b2, b3;
                ldsm4(sB + off, b0, b1, b2, b3);
#pragma unroll
                for (int mb = 0; mb < 2; mb++) {
                    mma16816(acc[mb][np*2+0], ahb[cur][mb], b0, b1);
                    mma16816(acc[mb][np*2+1], ahb[cur][mb], b2, b3);
                    if (EPI == 1) {
                        mma16816(acc[mb][np*2+0], alb[cur][mb], b0, b1);
                        mma16816(acc[mb][np*2+1], alb[cur][mb], b2, b3);
                    }
                }
            }
        }
        __syncthreads();
        stage++; if (stage >= 3) stage = 0;
    }

    // ---------------- epilogue ----------------
    const int mrow0 = bm + wm * 32 + (lane >> 2);
    const int ncol0 = bn + wn * 64 + (lane & 3) * 2;
#pragma unroll
    for (int mb = 0; mb < 2; mb++) {
#pragma unroll
        for (int n8 = 0; n8 < 8; n8++) {
            int n = ncol0 + n8 * 8;
            int m0 = mrow0 + mb * 16;
            float2 v0 = make_float2(acc[mb][n8][0], acc[mb][n8][1]);
            float2 v1 = make_float2(acc[mb][n8][2], acc[mb][n8][3]);
            if (EPI == 2) {
                *(float2*)(Cout + (size_t)m0 * H_ + n)       = v0;
                *(float2*)(Cout + (size_t)(m0 + 8) * H_ + n) = v1;
            } else if (bn < R_) {
                *(float2*)(g_xr + (size_t)m0 * R_ + n)       = v0;
                *(float2*)(g_xr + (size_t)(m0 + 8) * R_ + n) = v1;
            } else {
                v0.x = 0.5f * v0.x * (1.0f + erff(v0.x * 0.7071067811865476f));
                v0.y = 0.5f * v0.y * (1.0f + erff(v0.y * 0.7071067811865476f));
                v1.x = 0.5f * v1.x * (1.0f + erff(v1.x * 0.7071067811865476f));
                v1.y = 0.5f * v1.y * (1.0f + erff(v1.y * 0.7071067811865476f));
                *(float2*)(g_gy + (size_t)m0 * R_ + (n - R_))       = v0;
                *(float2*)(g_gy + (size_t)(m0 + 8) * R_ + (n - R_)) = v1;
            }
        }
    }
}
#define GEMM_SMEM1 (3*3*TILEB)   // 147456
#define GEMM_SMEM2 (3*2*TILEB)   // 98304

// ---------------- causal depthwise conv (CW=4) -> fp16 -----------------------
__global__ void conv_kernel(const float* __restrict__ conv_w,
                            const float* __restrict__ conv_b)
{
    size_t idx = (size_t)blockIdx.x * blockDim.x + threadIdx.x;
    int r = (int)(idx & (R_ - 1));
    size_t row = idx >> 11;
    int t = (int)(row & (S_ - 1));
    int b = (int)(row >> 12);
    float acc = conv_b[r];
#pragma unroll
    for (int i = 0; i < CW_; i++) {
        int tt = t - (CW_ - 1) + i;
        if (tt >= 0)
            acc += conv_w[i * R_ + r] * g_xr[((size_t)(b * S_ + tt)) * R_ + r];
    }
    g_xch[idx] = __float2half_rn(acc);
}

// ---------------- fused block-diag gate GEMM + nonlinearity ------------------
// grid (NB_, M_/128), 512 thr = 16 warps (wm 0..3 x wn 0..3 over N=256).
// Single-product fp16 MMA. wn>=2 hold ag_pre -> exchange via SMEM; wn<2 hold
// xg_pre and compute a, nx directly. No separate elementwise pass.
#define GW_SMEM 98304   // X 32K (2x16K) | W 64K (2x32K); ag exchange reuses 64K

__global__ __launch_bounds__(512) void gates_mma(
    const float* __restrict__ igb, const float* __restrict__ agb)
{
    extern __shared__ char smem[];
    const uint32_t smem_u = smem_to_u32(smem);
    float* smem_ag = (float*)smem;
    const int tid  = threadIdx.x;
    const int lane = tid & 31;
    const int wid  = tid >> 5;
    const int wm   = wid & 3;
    const int wn   = wid >> 2;
    const int nb   = blockIdx.x;
    const int bm   = blockIdx.y * 128;

    // load X [128x128] fp16 (2 chunks of 64 cols)
#pragma unroll
    for (int i = 0; i < 4; i++) {
        int u = i * 512 + tid;          // 0..2047
        int c2  = u >> 10;
        int row = (u >> 3) & 127;
        int un  = u & 7;
        const __half* src = g_xch + (size_t)(bm + row) * R_ + nb * 128 + c2 * 64 + un * 8;
        uint32_t dst = smem_u + c2 * 16384 + row * 128 + ((un ^ (row & 7)) * 16);
        asm volatile("cp.async.cg.shared.global [%0], [%1], 16;"
            :: "r"(dst), "l"(src) : "memory");
    }
    // load W [256x128] fp16 (2 chunks of 64 cols)
#pragma unroll
    for (int i = 0; i < 8; i++) {
        int u = i * 512 + tid;          // 0..4095
        int c2  = u >> 11;
        int row = (u >> 3) & 255;
        int un  = u & 7;
        const __half* src = g_gwh + (size_t)nb * 32768 + (size_t)row * 128 + c2 * 64 + un * 8;
        uint32_t dst = smem_u + 32768 + c2 * 32768 + row * 128 + ((un ^ (row & 7)) * 16);
        asm volatile("cp.async.cg.shared.global [%0], [%1], 16;"
            :: "r"(dst), "l"(src) : "memory");
    }
    asm volatile("cp.async.commit_group;" ::: "memory");
    asm volatile("cp.async.wait_group 0;" ::: "memory");
    __syncthreads();

    const int a_row = wm * 32 + (lane & 15);
    const int a_hf  = lane >> 4;
    const int b_row = wn * 64 + (lane & 7) + ((lane >> 4) << 3);
    const int b_hf  = (lane >> 3) & 1;

    float acc[2][8][4];
#pragma unroll
    for (int mb = 0; mb < 2; mb++)
#pragma unroll
        for (int n8 = 0; n8 < 8; n8++)
#pragma unroll
            for (int q = 0; q < 4; q++) acc[mb][n8][q] = 0.f;

#pragma unroll
    for (int c2 = 0; c2 < 2; c2++) {
        const uint32_t sX = smem_u + c2 * 16384;
        const uint32_t sW = smem_u + 32768 + c2 * 32768;
#pragma unroll
        for (int ks = 0; ks < 4; ks++) {
            uint32_t ah[2][4];
#pragma unroll
            for (int mb = 0; mb < 2; mb++) {
                int row = a_row + mb * 16;
                int un  = ks * 2 + a_hf;
                uint32_t off = row * 128 + ((un ^ (row & 7)) * 16);
                ldsm4(sX + off, ah[mb][0], ah[mb][1], ah[mb][2], ah[mb][3]);
            }
#pragma unroll
            for (int np = 0; np < 4; np++) {
                int row = b_row + np * 16;
                int un  = ks * 2 + b_hf;
                uint32_t off = row * 128 + ((un ^ (row & 7)) * 16);
                uint32_t b0, b1, b2, b3;
                ldsm4(sW + off, b0, b1, b2, b3);
#pragma unroll
                for (int mb = 0; mb < 2; mb++) {
                    mma16816(acc[mb][np*2+0], ah[mb], b0, b1);
                    mma16816(acc[mb][np*2+1], ah[mb], b2, b3);
                }
            }
        }
    }

    __syncthreads();   // MMA reads of SMEM done before ag overwrite

    const int mrow_l = wm * 32 + (lane >> 2);
    const int col0   = wn * 64 + (lane & 3) * 2;   // 0..255

    if (wn >= 2) {
        // stash ag pre-activations in SMEM
#pragma unroll
        for (int mb = 0; mb < 2; mb++) {
#pragma unroll
            for (int n8 = 0; n8 < 8; n8++) {
                int colr = (col0 - 128) + n8 * 8;
                int ml = mrow_l + mb * 16;
                *(float2*)(smem_ag + ml * 128 + colr)       =
                    make_float2(acc[mb][n8][0], acc[mb][n8][1]);
                *(float2*)(smem_ag + (ml + 8) * 128 + colr) =
                    make_float2(acc[mb][n8][2], acc[mb][n8][3]);
            }
        }
    }
    __syncthreads();
    if (wn < 2) {
#pragma unroll
        for (int mb = 0; mb < 2; mb++) {
#pragma unroll
            for (int n8 = 0; n8 < 8; n8++) {
                int colr = col0 + n8 * 8;
#pragma unroll
                for (int half_row = 0; half_row < 2; half_row++) {
                    int ml = mrow_l + mb * 16 + half_row * 8;
                    int m  = bm + ml;
                    float xg0 = acc[mb][n8][half_row*2+0];
                    float xg1 = acc[mb][n8][half_row*2+1];
                    float2 agv = *(float2*)(smem_ag + ml * 128 + colr);
#pragma unroll
                    for (int e = 0; e < 2; e++) {
                        int r = nb * 128 + colr + e;
                        float xg = (e ? xg1 : xg0) + igb[r];
                        float ag = (e ? agv.y : agv.x) + agb[r];
                        float sp = g_sp[r];
                        float ga = __fdividef(1.f, 1.f + __expf(-ag));
                        float la = -8.f * ga * sp;
                        float a  = __expf(la);
                        float mult = sqrtf(fmaxf(fmaf(-a, a, 1.f), 0.f));
                        float gx = __fdividef(1.f, 1.f + __expf(-xg));
                        float xv = __half2float(g_xch[(size_t)m * R_ + r]);
                        g_av[(size_t)m * R_ + r] = a;
                        g_nx[(size_t)m * R_ + r] = xv * gx * mult;
                    }
                }
            }
        }
    }
}

// ---------------- chunked linear-recurrence scan ----------------------------
__global__ void scanA()
{
    int r = blockIdx.x * 256 + threadIdx.x;
    int chunk = blockIdx.y;
    int b = blockIdx.z;
    size_t base = ((size_t)(b * S_ + chunk * CHL)) * R_ + r;
    const float* __restrict__ pa = g_av + base;
    const float* __restrict__ px = g_nx + base;
    float A = 1.f, Bv = 0.f;
#pragma unroll 4
    for (int t = 0; t < CHL; t++) {
        float av = pa[(size_t)t * R_];
        float xv = px[(size_t)t * R_];
        Bv = av * Bv + xv;
        A *= av;
    }
    int ch = b * R_ + r;
    g_Asum[ch * NCHUNK + chunk] = A;
    g_Bsum[ch * NCHUNK + chunk] = Bv;
}

__global__ void scanB()
{
    int ch = blockIdx.x * 256 + threadIdx.x;
    float h = 0.f;
#pragma unroll
    for (int c = 0; c < NCHUNK; c++) {
        g_carry[ch * NCHUNK + c] = h;
        h = g_Asum[ch * NCHUNK + c] * h + g_Bsum[ch * NCHUNK + c];
    }
}

__global__ void scanC()
{
    int r = blockIdx.x * 256 + threadIdx.x;
    int chunk = blockIdx.y;
    int b = blockIdx.z;
    size_t base = ((size_t)(b * S_ + chunk * CHL)) * R_ + r;
    const float* __restrict__ pa = g_av + base;
    const float* __restrict__ px = g_nx + base;
    const float* __restrict__ pg = g_gy + base;
    __half* __restrict__ ph = g_hgh + base;
    int ch = b * R_ + r;
    float h = g_carry[ch * NCHUNK + chunk];
#pragma unroll 4
    for (int t = 0; t < CHL; t++) {
        float av = pa[(size_t)t * R_];
        float xv = px[(size_t)t * R_];
        h = av * h + xv;
        ph[(size_t)t * R_] = __float2half_rn(h * pg[(size_t)t * R_]);
    }
}

// ---------------- host launcher ---------------------------------------------
extern "C" void kernel_launch(void* const* d_in, const int* in_sizes, int n_in,
                              void* d_out, int out_size)
{
    const float* x       = (const float*)d_in[0];
    const float* W_xy    = (const float*)d_in[1];
    const float* ig_w    = (const float*)d_in[2];
    const float* ig_b    = (const float*)d_in[3];
    const float* ag_w    = (const float*)d_in[4];
    const float* ag_b    = (const float*)d_in[5];
    const float* a_param = (const float*)d_in[6];
    const float* conv_w  = (const float*)d_in[7];
    const float* conv_b  = (const float*)d_in[8];
    const float* W_resid = (const float*)d_in[9];
    float* out = (float*)d_out;

    cudaFuncSetAttribute(gemm_tc<1>, cudaFuncAttributeMaxDynamicSharedMemorySize, GEMM_SMEM1);
    cudaFuncSetAttribute(gemm_tc<2>, cudaFuncAttributeMaxDynamicSharedMemorySize, GEMM_SMEM2);
    cudaFuncSetAttribute(gates_mma,  cudaFuncAttributeMaxDynamicSharedMemorySize, GW_SMEM);

    // 0) conversions
    split_x<<<(M_ * H_ / 4) / 256, 256>>>((const float4*)x);
    cvt_half<0><<<(2 * R_ * H_ / 4) / 256, 256>>>((const float4*)W_xy);
    cvt_half<1><<<(H_ * R_ / 4) / 256, 256>>>((const float4*)W_resid);
    split_gatew<<<(NB_ * BW_ * BW_) / 256, 256>>>(ig_w, ag_w);
    prep_sp<<<R_ / 256, 256>>>(a_param);

    // 1) xy = x @ W_xy^T  (fp16 2-product; -> g_xr, gelu -> g_gy)
    {
        dim3 grid(2 * R_ / 128, M_ / 128);   // (32, 64)
        gemm_tc<1><<<grid, 256, GEMM_SMEM1>>>(nullptr);
    }
    // 2) causal depthwise conv -> fp16 xc
    conv_kernel<<<(unsigned)((size_t)M_ * R_ / 256), 256>>>(conv_w, conv_b);
    // 3) fused block-diag gate GEMM + RG-LRU nonlinearity
    {
        dim3 grid(NB_, M_ / 128);
        gates_mma<<<grid, 512, GW_SMEM>>>(ig_b, ag_b);
    }
    // 4) chunked scan, fused * gelu(y), fp16 output
    {
        dim3 gA(R_ / 256, NCHUNK, B_);       // (8, 32, 2)
        scanA<<<gA, 256>>>();
        scanB<<<NCH / 256, 256>>>();
        scanC<<<gA, 256>>>();
    }
    // 5) out = hg @ W_resid^T  (fp16 1-product)
    {
        dim3 grid(H_ / 128, M_ / 128);       // (16, 64)
        gemm_tc<2><<<grid, 256, GEMM_SMEM2>>>(out);
    }
}

// round 17
// speedup vs baseline: 2.0571x; 1.1100x over previous
#include <cuda_runtime.h>
#include <cuda_fp16.h>
#include <math.h>
#include <stdint.h>

// ---------------- problem constants ----------------
#define B_  2
#define S_  4096
#define H_  2048
#define R_  2048
#define NB_ 16
#define BW_ 128
#define CW_ 4
#define M_  (B_*S_)        // 8192
#define NCHUNK 64
#define CHL (S_/NCHUNK)    // 64
#define NCH (B_*R_)        // 4096
#define KDIM 2048
#define KC  64             // K elements per SMEM chunk
#define NKC (KDIM/KC)      // 32 chunks

// ---------------- scratch (device globals; no allocations allowed) ----------
__device__ float g_xr[(size_t)M_*R_];   // GEMM1 out (xr), feeds conv
__device__ float g_gy[(size_t)M_*R_];   // gelu(y)
__device__ float g_av[(size_t)M_*R_];   // a_t
__device__ float g_nx[(size_t)M_*R_];   // norm_x_t
__device__ float g_Asum[NCH*NCHUNK];
__device__ float g_Bsum[NCH*NCHUNK];
__device__ float g_carry[NCH*NCHUNK];
__device__ float g_sp[R_];              // softplus(a_param), per channel

__device__ __half g_xh [(size_t)M_*H_];     // x hi (fp16 split)
__device__ __half g_xl [(size_t)M_*H_];     // x lo
__device__ __half g_wxyh[(size_t)2*R_*H_];  // W_xy fp16
__device__ __half g_wrh[(size_t)H_*R_];     // W_resid fp16
__device__ __half g_hgh[(size_t)M_*R_];     // h*gelu(y) fp16
__device__ __half g_xch[(size_t)M_*R_];     // conv out fp16
__device__ __half g_gwh[(size_t)NB_*256*128]; // gate W [nb][n=256][k=128] fp16

// ---------------- helpers ----------------------------------------------------
__device__ __forceinline__ uint32_t smem_to_u32(const void* p) {
    uint32_t a;
    asm("{ .reg .u64 t; cvta.to.shared.u64 t, %1; cvt.u32.u64 %0, t; }"
        : "=r"(a) : "l"(p));
    return a;
}

__device__ __forceinline__ void ldsm4(uint32_t addr,
    uint32_t& r0, uint32_t& r1, uint32_t& r2, uint32_t& r3)
{
    asm volatile("ldmatrix.sync.aligned.m8n8.x4.shared.b16 {%0,%1,%2,%3}, [%4];"
        : "=r"(r0), "=r"(r1), "=r"(r2), "=r"(r3) : "r"(addr));
}

__device__ __forceinline__ void mma16816(float* c,
    const uint32_t* a, uint32_t b0, uint32_t b1)
{
    asm volatile(
        "mma.sync.aligned.m16n8k16.row.col.f32.f16.f16.f32 "
        "{%0,%1,%2,%3}, {%4,%5,%6,%7}, {%8,%9}, {%0,%1,%2,%3};"
        : "+f"(c[0]), "+f"(c[1]), "+f"(c[2]), "+f"(c[3])
        : "r"(a[0]), "r"(a[1]), "r"(a[2]), "r"(a[3]), "r"(b0), "r"(b1));
}

// ---------------- conversion kernels ----------------------------------------
__global__ void split_x(const float4* __restrict__ src)
{
    int i = blockIdx.x * 256 + threadIdx.x;
    float4 v = src[i];
    __half h[4], l[4];
    h[0] = __float2half_rn(v.x); l[0] = __float2half_rn(v.x - __half2float(h[0]));
    h[1] = __float2half_rn(v.y); l[1] = __float2half_rn(v.y - __half2float(h[1]));
    h[2] = __float2half_rn(v.z); l[2] = __float2half_rn(v.z - __half2float(h[2]));
    h[3] = __float2half_rn(v.w); l[3] = __float2half_rn(v.w - __half2float(h[3]));
    *(uint2*)(g_xh + 4ull * i) = *(uint2*)h;
    *(uint2*)(g_xl + 4ull * i) = *(uint2*)l;
}

template <int DST>
__global__ void cvt_half(const float4* __restrict__ src)
{
    int i = blockIdx.x * 256 + threadIdx.x;
    float4 v = src[i];
    __half h[4];
    h[0] = __float2half_rn(v.x); h[1] = __float2half_rn(v.y);
    h[2] = __float2half_rn(v.z); h[3] = __float2half_rn(v.w);
    __half* dst = (DST == 0) ? g_wxyh : g_wrh;
    *(uint2*)(dst + 4ull * i) = *(uint2*)h;
}

__global__ void split_gatew(const float* __restrict__ igw,
                            const float* __restrict__ agw)
{
    int idx = blockIdx.x * 256 + threadIdx.x;
    int nb = idx >> 14;
    int i  = (idx >> 7) & 127;
    int j  = idx & 127;
    size_t d1 = (size_t)nb * 32768 + (size_t)j * 128 + i;
    g_gwh[d1]             = __float2half_rn(igw[idx]);
    g_gwh[d1 + 128 * 128] = __float2half_rn(agw[idx]);
}

__global__ void prep_sp(const float* __restrict__ ap)
{
    int r = blockIdx.x * 256 + threadIdx.x;
    float a = ap[r];
    g_sp[r] = (a > 20.f) ? a : log1pf(expf(a));
}

// ---------------- fp16 HMMA GEMM (TN) ----------------------------------------
// 128x128 tile, 8 warps (4x2), warp 32x64. 96KB smem -> 2 CTAs/SM.
// EPI 1: A = x split (hi+lo, 2 products), B = W_xy; 2-stage x 3 tiles.
// EPI 2: A = hg (1 product), B = W_resid; 3-stage x 2 tiles.
#define TILEB   16384
#define GEMM_SMEM 98304

__device__ __forceinline__ void load_tile_async(
    const __half* __restrict__ g, int row0, int kc, uint32_t sdst, int tid)
{
#pragma unroll
    for (int i = 0; i < 4; i++) {
        int u = i * 256 + tid;
        int row = u >> 3;
        int un  = u & 7;
        const __half* src = g + (size_t)(row0 + row) * KDIM + kc * KC + un * 8;
        uint32_t dst = sdst + row * 128 + ((un ^ (row & 7)) * 16);
        asm volatile("cp.async.cg.shared.global [%0], [%1], 16;"
            :: "r"(dst), "l"(src) : "memory");
    }
}

template <int EPI>
__global__ __launch_bounds__(256, 2) void gemm_tc(float* __restrict__ Cout)
{
    constexpr int NT   = (EPI == 1) ? 3 : 2;      // tiles per stage
    constexpr int NSTG = (EPI == 1) ? 2 : 3;      // pipeline stages
    constexpr int STAGEB = NT * TILEB;
    extern __shared__ char smem[];
    const uint32_t smem_u = smem_to_u32(smem);
    const int tid  = threadIdx.x;
    const int lane = tid & 31;
    const int wm   = (tid >> 5) & 3;
    const int wn   = tid >> 7;
    const int bm = blockIdx.y * 128;
    const int bn = blockIdx.x * 128;

    const __half *Ah, *Al, *Bt;
    if (EPI == 1) { Ah = g_xh;  Al = g_xl; Bt = g_wxyh; }
    else          { Ah = g_hgh; Al = nullptr; Bt = g_wrh; }

    float acc[2][8][4];
#pragma unroll
    for (int mb = 0; mb < 2; mb++)
#pragma unroll
        for (int n8 = 0; n8 < 8; n8++)
#pragma unroll
            for (int q = 0; q < 4; q++) acc[mb][n8][q] = 0.f;

    // prologue: fill NSTG-1 stages
#pragma unroll
    for (int p = 0; p < NSTG - 1; p++) {
        uint32_t sb = smem_u + p * STAGEB;
        load_tile_async(Ah, bm, p, sb, tid);
        if (EPI == 1) load_tile_async(Al, bm, p, sb + TILEB, tid);
        load_tile_async(Bt, bn, p, sb + (NT - 1) * TILEB, tid);
        asm volatile("cp.async.commit_group;" ::: "memory");
    }

    const int a_row = wm * 32 + (lane & 15);
    const int a_hf  = lane >> 4;
    const int b_row = wn * 64 + (lane & 7) + ((lane >> 4) << 3);
    const int b_hf  = (lane >> 3) & 1;

    int stage = 0;
    for (int c = 0; c < NKC; c++) {
        if (c + NSTG - 1 < NKC) {
            int s2 = stage + NSTG - 1; if (s2 >= NSTG) s2 -= NSTG;
            uint32_t sb = smem_u + s2 * STAGEB;
            load_tile_async(Ah, bm, c + NSTG - 1, sb, tid);
            if (EPI == 1) load_tile_async(Al, bm, c + NSTG - 1, sb + TILEB, tid);
            load_tile_async(Bt, bn, c + NSTG - 1, sb + (NT - 1) * TILEB, tid);
            asm volatile("cp.async.commit_group;" ::: "memory");
            if (NSTG == 2) asm volatile("cp.async.wait_group 1;" ::: "memory");
            else           asm volatile("cp.async.wait_group 2;" ::: "memory");
        } else if (NSTG == 3 && c + 1 < NKC) {
            asm volatile("cp.async.wait_group 1;" ::: "memory");
        } else {
            asm volatile("cp.async.wait_group 0;" ::: "memory");
        }
        __syncthreads();

        const uint32_t sA = smem_u + stage * STAGEB;
        const uint32_t sB = sA + (NT - 1) * TILEB;

        uint32_t ahb[2][2][4], alb[2][2][4];
#pragma unroll
        for (int mb = 0; mb < 2; mb++) {
            int row = a_row + mb * 16;
            uint32_t off = row * 128 + ((a_hf ^ (row & 7)) * 16);
            ldsm4(sA + off, ahb[0][mb][0], ahb[0][mb][1], ahb[0][mb][2], ahb[0][mb][3]);
            if (EPI == 1)
                ldsm4(sA + TILEB + off, alb[0][mb][0], alb[0][mb][1], alb[0][mb][2], alb[0][mb][3]);
        }

#pragma unroll
        for (int ks = 0; ks < 4; ks++) {
            const int cur = ks & 1;
            if (ks < 3) {
#pragma unroll
                for (int mb = 0; mb < 2; mb++) {
                    int row = a_row + mb * 16;
                    int un  = (ks + 1) * 2 + a_hf;
                    uint32_t off = row * 128 + ((un ^ (row & 7)) * 16);
                    ldsm4(sA + off, ahb[cur^1][mb][0], ahb[cur^1][mb][1],
                                    ahb[cur^1][mb][2], ahb[cur^1][mb][3]);
                    if (EPI == 1)
                        ldsm4(sA + TILEB + off, alb[cur^1][mb][0], alb[cur^1][mb][1],
                                                alb[cur^1][mb][2], alb[cur^1][mb][3]);
                }
            }
#pragma unroll
            for (int np = 0; np < 4; np++) {
                int row = b_row + np * 16;
                int un  = ks * 2 + b_hf;
                uint32_t off = row * 128 + ((un ^ (row & 7)) * 16);
                uint32_t b0, b1, b2, b3;
                ldsm4(sB + off, b0, b1, b2, b3);
#pragma unroll
                for (int mb = 0; mb < 2; mb++) {
                    mma16816(acc[mb][np*2+0], ahb[cur][mb], b0, b1);
                    mma16816(acc[mb][np*2+1], ahb[cur][mb], b2, b3);
                    if (EPI == 1) {
                        mma16816(acc[mb][np*2+0], alb[cur][mb], b0, b1);
                        mma16816(acc[mb][np*2+1], alb[cur][mb], b2, b3);
                    }
                }
            }
        }
        __syncthreads();
        stage++; if (stage >= NSTG) stage = 0;
    }

    // ---------------- epilogue ----------------
    const int mrow0 = bm + wm * 32 + (lane >> 2);
    const int ncol0 = bn + wn * 64 + (lane & 3) * 2;
#pragma unroll
    for (int mb = 0; mb < 2; mb++) {
#pragma unroll
        for (int n8 = 0; n8 < 8; n8++) {
            int n = ncol0 + n8 * 8;
            int m0 = mrow0 + mb * 16;
            float2 v0 = make_float2(acc[mb][n8][0], acc[mb][n8][1]);
            float2 v1 = make_float2(acc[mb][n8][2], acc[mb][n8][3]);
            if (EPI == 2) {
                *(float2*)(Cout + (size_t)m0 * H_ + n)       = v0;
                *(float2*)(Cout + (size_t)(m0 + 8) * H_ + n) = v1;
            } else if (bn < R_) {
                *(float2*)(g_xr + (size_t)m0 * R_ + n)       = v0;
                *(float2*)(g_xr + (size_t)(m0 + 8) * R_ + n) = v1;
            } else {
                v0.x = 0.5f * v0.x * (1.0f + erff(v0.x * 0.7071067811865476f));
                v0.y = 0.5f * v0.y * (1.0f + erff(v0.y * 0.7071067811865476f));
                v1.x = 0.5f * v1.x * (1.0f + erff(v1.x * 0.7071067811865476f));
                v1.y = 0.5f * v1.y * (1.0f + erff(v1.y * 0.7071067811865476f));
                *(float2*)(g_gy + (size_t)m0 * R_ + (n - R_))       = v0;
                *(float2*)(g_gy + (size_t)(m0 + 8) * R_ + (n - R_)) = v1;
            }
        }
    }
}

// ---------------- causal depthwise conv (CW=4) -> fp16, float4 --------------
__global__ void conv_kernel(const float* __restrict__ conv_w,
                            const float* __restrict__ conv_b)
{
    size_t idx = (size_t)blockIdx.x * blockDim.x + threadIdx.x;  // over M_*R_/4
    int r4 = (int)(idx & (R_/4 - 1));
    size_t row = idx >> 9;             // / (R_/4)
    int t = (int)(row & (S_ - 1));
    int b = (int)(row >> 12);
    float4 acc = *(const float4*)(conv_b + 4 * r4);
#pragma unroll
    for (int i = 0; i < CW_; i++) {
        int tt = t - (CW_ - 1) + i;
        if (tt >= 0) {
            float4 w = *(const float4*)(conv_w + i * R_ + 4 * r4);
            float4 v = *(const float4*)(g_xr + ((size_t)(b * S_ + tt)) * R_ + 4 * r4);
            acc.x += w.x * v.x; acc.y += w.y * v.y;
            acc.z += w.z * v.z; acc.w += w.w * v.w;
        }
    }
    __half h[4];
    h[0] = __float2half_rn(acc.x); h[1] = __float2half_rn(acc.y);
    h[2] = __float2half_rn(acc.z); h[3] = __float2half_rn(acc.w);
    *(uint2*)(g_xch + 4 * idx) = *(uint2*)h;
}

// ---------------- fused block-diag gate GEMM + nonlinearity ------------------
#define GW_SMEM 98304

__global__ __launch_bounds__(512) void gates_mma(
    const float* __restrict__ igb, const float* __restrict__ agb)
{
    extern __shared__ char smem[];
    const uint32_t smem_u = smem_to_u32(smem);
    float* smem_ag = (float*)smem;
    const int tid  = threadIdx.x;
    const int lane = tid & 31;
    const int wid  = tid >> 5;
    const int wm   = wid & 3;
    const int wn   = wid >> 2;
    const int nb   = blockIdx.x;
    const int bm   = blockIdx.y * 128;

#pragma unroll
    for (int i = 0; i < 4; i++) {
        int u = i * 512 + tid;
        int c2  = u >> 10;
        int row = (u >> 3) & 127;
        int un  = u & 7;
        const __half* src = g_xch + (size_t)(bm + row) * R_ + nb * 128 + c2 * 64 + un * 8;
        uint32_t dst = smem_u + c2 * 16384 + row * 128 + ((un ^ (row & 7)) * 16);
        asm volatile("cp.async.cg.shared.global [%0], [%1], 16;"
            :: "r"(dst), "l"(src) : "memory");
    }
#pragma unroll
    for (int i = 0; i < 8; i++) {
        int u = i * 512 + tid;
        int c2  = u >> 11;
        int row = (u >> 3) & 255;
        int un  = u & 7;
        const __half* src = g_gwh + (size_t)nb * 32768 + (size_t)row * 128 + c2 * 64 + un * 8;
        uint32_t dst = smem_u + 32768 + c2 * 32768 + row * 128 + ((un ^ (row & 7)) * 16);
        asm volatile("cp.async.cg.shared.global [%0], [%1], 16;"
            :: "r"(dst), "l"(src) : "memory");
    }
    asm volatile("cp.async.commit_group;" ::: "memory");
    asm volatile("cp.async.wait_group 0;" ::: "memory");
    __syncthreads();

    const int a_row = wm * 32 + (lane & 15);
    const int a_hf  = lane >> 4;
    const int b_row = wn * 64 + (lane & 7) + ((lane >> 4) << 3);
    const int b_hf  = (lane >> 3) & 1;

    float acc[2][8][4];
#pragma unroll
    for (int mb = 0; mb < 2; mb++)
#pragma unroll
        for (int n8 = 0; n8 < 8; n8++)
#pragma unroll
            for (int q = 0; q < 4; q++) acc[mb][n8][q] = 0.f;

#pragma unroll
    for (int c2 = 0; c2 < 2; c2++) {
        const uint32_t sX = smem_u + c2 * 16384;
        const uint32_t sW = smem_u + 32768 + c2 * 32768;
#pragma unroll
        for (int ks = 0; ks < 4; ks++) {
            uint32_t ah[2][4];
#pragma unroll
            for (int mb = 0; mb < 2; mb++) {
                int row = a_row + mb * 16;
                int un  = ks * 2 + a_hf;
                uint32_t off = row * 128 + ((un ^ (row & 7)) * 16);
                ldsm4(sX + off, ah[mb][0], ah[mb][1], ah[mb][2], ah[mb][3]);
            }
#pragma unroll
            for (int np = 0; np < 4; np++) {
                int row = b_row + np * 16;
                int un  = ks * 2 + b_hf;
                uint32_t off = row * 128 + ((un ^ (row & 7)) * 16);
                uint32_t b0, b1, b2, b3;
                ldsm4(sW + off, b0, b1, b2, b3);
#pragma unroll
                for (int mb = 0; mb < 2; mb++) {
                    mma16816(acc[mb][np*2+0], ah[mb], b0, b1);
                    mma16816(acc[mb][np*2+1], ah[mb], b2, b3);
                }
            }
        }
    }

    __syncthreads();

    const int mrow_l = wm * 32 + (lane >> 2);
    const int col0   = wn * 64 + (lane & 3) * 2;

    if (wn >= 2) {
#pragma unroll
        for (int mb = 0; mb < 2; mb++) {
#pragma unroll
            for (int n8 = 0; n8 < 8; n8++) {
                int colr = (col0 - 128) + n8 * 8;
                int ml = mrow_l + mb * 16;
                *(float2*)(smem_ag + ml * 128 + colr)       =
                    make_float2(acc[mb][n8][0], acc[mb][n8][1]);
                *(float2*)(smem_ag + (ml + 8) * 128 + colr) =
                    make_float2(acc[mb][n8][2], acc[mb][n8][3]);
            }
        }
    }
    __syncthreads();
    if (wn < 2) {
#pragma unroll
        for (int mb = 0; mb < 2; mb++) {
#pragma unroll
            for (int n8 = 0; n8 < 8; n8++) {
                int colr = col0 + n8 * 8;
#pragma unroll
                for (int half_row = 0; half_row < 2; half_row++) {
                    int ml = mrow_l + mb * 16 + half_row * 8;
                    int m  = bm + ml;
                    float xg0 = acc[mb][n8][half_row*2+0];
                    float xg1 = acc[mb][n8][half_row*2+1];
                    float2 agv = *(float2*)(smem_ag + ml * 128 + colr);
#pragma unroll
                    for (int e = 0; e < 2; e++) {
                        int r = nb * 128 + colr + e;
                        float xg = (e ? xg1 : xg0) + igb[r];
                        float ag = (e ? agv.y : agv.x) + agb[r];
                        float sp = g_sp[r];
                        float ga = __fdividef(1.f, 1.f + __expf(-ag));
                        float la = -8.f * ga * sp;
                        float a  = __expf(la);
                        float mult = sqrtf(fmaxf(fmaf(-a, a, 1.f), 0.f));
                        float gx = __fdividef(1.f, 1.f + __expf(-xg));
                        float xv = __half2float(g_xch[(size_t)m * R_ + r]);
                        g_av[(size_t)m * R_ + r] = a;
                        g_nx[(size_t)m * R_ + r] = xv * gx * mult;
                    }
                }
            }
        }
    }
}

// ---------------- chunked linear-recurrence scan (float4) --------------------
__global__ void scanA()
{
    int r4 = blockIdx.x * 256 + threadIdx.x;     // channel-group 0..511
    int chunk = blockIdx.y;
    int b = blockIdx.z;
    size_t base = ((size_t)(b * S_ + chunk * CHL)) * R_ + 4 * r4;
    const float* __restrict__ pa = g_av + base;
    const float* __restrict__ px = g_nx + base;
    float4 A = make_float4(1.f, 1.f, 1.f, 1.f);
    float4 Bv = make_float4(0.f, 0.f, 0.f, 0.f);
#pragma unroll 4
    for (int t = 0; t < CHL; t++) {
        float4 av = *(const float4*)(pa + (size_t)t * R_);
        float4 xv = *(const float4*)(px + (size_t)t * R_);
        Bv.x = av.x * Bv.x + xv.x;  A.x *= av.x;
        Bv.y = av.y * Bv.y + xv.y;  A.y *= av.y;
        Bv.z = av.z * Bv.z + xv.z;  A.z *= av.z;
        Bv.w = av.w * Bv.w + xv.w;  A.w *= av.w;
    }
    int ch = b * R_ + 4 * r4;
#pragma unroll
    for (int e = 0; e < 4; e++) {
        float Ae = (e == 0) ? A.x : (e == 1) ? A.y : (e == 2) ? A.z : A.w;
        float Be = (e == 0) ? Bv.x : (e == 1) ? Bv.y : (e == 2) ? Bv.z : Bv.w;
        g_Asum[(ch + e) * NCHUNK + chunk] = Ae;
        g_Bsum[(ch + e) * NCHUNK + chunk] = Be;
    }
}

__global__ void scanB()
{
    int ch = blockIdx.x * 256 + threadIdx.x;
    float h = 0.f;
#pragma unroll
    for (int c = 0; c < NCHUNK; c++) {
        g_carry[ch * NCHUNK + c] = h;
        h = g_Asum[ch * NCHUNK + c] * h + g_Bsum[ch * NCHUNK + c];
    }
}

__global__ void scanC()
{
    int r4 = blockIdx.x * 256 + threadIdx.x;
    int chunk = blockIdx.y;
    int b = blockIdx.z;
    size_t base = ((size_t)(b * S_ + chunk * CHL)) * R_ + 4 * r4;
    const float* __restrict__ pa = g_av + base;
    const float* __restrict__ px = g_nx + base;
    const float* __restrict__ pg = g_gy + base;
    __half* __restrict__ ph = g_hgh + base;
    int ch = b * R_ + 4 * r4;
    float4 h;
    h.x = g_carry[(ch + 0) * NCHUNK + chunk];
    h.y = g_carry[(ch + 1) * NCHUNK + chunk];
    h.z = g_carry[(ch + 2) * NCHUNK + chunk];
    h.w = g_carry[(ch + 3) * NCHUNK + chunk];
#pragma unroll 4
    for (int t = 0; t < CHL; t++) {
        float4 av = *(const float4*)(pa + (size_t)t * R_);
        float4 xv = *(const float4*)(px + (size_t)t * R_);
        float4 gy = *(const float4*)(pg + (size_t)t * R_);
        h.x = av.x * h.x + xv.x;
        h.y = av.y * h.y + xv.y;
        h.z = av.z * h.z + xv.z;
        h.w = av.w * h.w + xv.w;
        __half o[4];
        o[0] = __float2half_rn(h.x * gy.x);
        o[1] = __float2half_rn(h.y * gy.y);
        o[2] = __float2half_rn(h.z * gy.z);
        o[3] = __float2half_rn(h.w * gy.w);
        *(uint2*)(ph + (size_t)t * R_) = *(uint2*)o;
    }
}

// ---------------- host launcher ---------------------------------------------
extern "C" void kernel_launch(void* const* d_in, const int* in_sizes, int n_in,
                              void* d_out, int out_size)
{
    const float* x       = (const float*)d_in[0];
    const float* W_xy    = (const float*)d_in[1];
    const float* ig_w    = (const float*)d_in[2];
    const float* ig_b    = (const float*)d_in[3];
    const float* ag_w    = (const float*)d_in[4];
    const float* ag_b    = (const float*)d_in[5];
    const float* a_param = (const float*)d_in[6];
    const float* conv_w  = (const float*)d_in[7];
    const float* conv_b  = (const float*)d_in[8];
    const float* W_resid = (const float*)d_in[9];
    float* out = (float*)d_out;

    cudaFuncSetAttribute(gemm_tc<1>, cudaFuncAttributeMaxDynamicSharedMemorySize, GEMM_SMEM);
    cudaFuncSetAttribute(gemm_tc<2>, cudaFuncAttributeMaxDynamicSharedMemorySize, GEMM_SMEM);
    cudaFuncSetAttribute(gates_mma,  cudaFuncAttributeMaxDynamicSharedMemorySize, GW_SMEM);

    // 0) conversions
    split_x<<<(M_ * H_ / 4) / 256, 256>>>((const float4*)x);
    cvt_half<0><<<(2 * R_ * H_ / 4) / 256, 256>>>((const float4*)W_xy);
    cvt_half<1><<<(H_ * R_ / 4) / 256, 256>>>((const float4*)W_resid);
    split_gatew<<<(NB_ * BW_ * BW_) / 256, 256>>>(ig_w, ag_w);
    prep_sp<<<R_ / 256, 256>>>(a_param);

    // 1) xy = x @ W_xy^T  (fp16 2-product; -> g_xr, gelu -> g_gy)
    {
        dim3 grid(2 * R_ / 128, M_ / 128);   // (32, 64)
        gemm_tc<1><<<grid, 256, GEMM_SMEM>>>(nullptr);
    }
    // 2) causal depthwise conv -> fp16 xc
    conv_kernel<<<(unsigned)((size_t)M_ * R_ / 4 / 256), 256>>>(conv_w, conv_b);
    // 3) fused block-diag gate GEMM + RG-LRU nonlinearity
    {
        dim3 grid(NB_, M_ / 128);
        gates_mma<<<grid, 512, GW_SMEM>>>(ig_b, ag_b);
    }
    // 4) chunked scan, fused * gelu(y), fp16 output
    {
        dim3 gA(R_ / 4 / 256, NCHUNK, B_);   // (2, 64, 2)
        scanA<<<gA, 256>>>();
        scanB<<<NCH / 256, 256>>>();
        scanC<<<gA, 256>>>();
    }
    // 5) out = hg @ W_resid^T  (fp16 1-product)
    {
        dim3 grid(H_ / 128, M_ / 128);       // (16, 64)
        gemm_tc<2><<<grid, 256, GEMM_SMEM>>>(out);
    }
}